// round 2
// baseline (speedup 1.0000x reference)
#include <cuda_runtime.h>
#include <math.h>

// ---------------- problem constants ----------------
constexpr int Bv = 16, Nv = 2000, Wv = 32, Fv = 5;
constexpr int TH = 128, SH = 64, HEADS = 4;
constexpr int Mn = Bv * Nv;              // 32000 nodes
constexpr int EB = 32000;                // base edges per graph
constexpr int ET = Bv * EB + Mn;         // 544000 total edges (incl. self loops)

// ---------------- device scratch (no allocations allowed) ----------------
__device__ float g_h0[(size_t)Mn * TH];
__device__ float g_h1[(size_t)Mn * TH];
__device__ float g_xp[(size_t)Mn * SH];
__device__ float g_asrc[Mn * HEADS];
__device__ float g_adst[Mn * HEADS];
__device__ float g_den[Mn * HEADS];
__device__ float g_agg[(size_t)Mn * SH];
__device__ float g_WtH0[TH * 3 * TH];    // [k=128][j=384], j = gate*128+col
__device__ float g_WtI1[TH * 3 * TH];
__device__ float g_WtH1[TH * 3 * TH];
__device__ int   g_ei_is64;              // edge-index dtype flag

// ---------------- probe: detect int32 vs int64 edge index ----------------
// If buffer is int64 (values < 2000), every odd 32-bit word is 0.
// If int32, odd words are random node ids — all-zero probability ~0.
__global__ void detect_ei_kernel(const int* __restrict__ w) {
    __shared__ int nz;
    if (threadIdx.x == 0) nz = 0;
    __syncthreads();
    // inspect first 2048 words (within bounds for both dtypes: >= 64000 words)
    for (int i = threadIdx.x; i < 2048; i += blockDim.x)
        if ((i & 1) && w[i] != 0) atomicOr(&nz, 1);
    __syncthreads();
    if (threadIdx.x == 0) g_ei_is64 = nz ? 0 : 1;
}

// ---------------- prep: transpose GRU weights to k-major ----------------
__global__ void prep_kernel(const float* __restrict__ Whh0,
                            const float* __restrict__ Wih1,
                            const float* __restrict__ Whh1) {
    int i = blockIdx.x * blockDim.x + threadIdx.x;
    if (i < TH * 3 * TH) {
        int j = i % (3 * TH);
        int k = i / (3 * TH);
        g_WtH0[k * 384 + j] = Whh0[j * TH + k];
        g_WtI1[k * 384 + j] = Wih1[j * TH + k];
        g_WtH1[k * 384 + j] = Whh1[j * TH + k];
    }
}

// ---------------- zero state + accumulators ----------------
__global__ void zero_all_kernel() {
    size_t stride = (size_t)gridDim.x * blockDim.x;
    for (size_t i = (size_t)blockIdx.x * blockDim.x + threadIdx.x;
         i < (size_t)Mn * TH; i += stride) {
        g_h0[i] = 0.f;
        g_h1[i] = 0.f;
        if (i < (size_t)Mn * SH) g_agg[i] = 0.f;
        if (i < (size_t)Mn * HEADS) g_den[i] = 0.f;
    }
}

// ---------------- GRU cell kernels ----------------
// Block = 64 nodes, 512 threads. Thread (ty,tx): rows ty*4..+3, cols tx*4..+3.
// Accumulators: aR,aZ (gi+gh summed), aI (input n-part), aN (hidden n-part).

#define GATE_FMA(c, comp)                               \
    aR[r][c] = fmaf(av, wiR.comp, aR[r][c]);            \
    aR[r][c] = fmaf(hv, whR.comp, aR[r][c]);            \
    aZ[r][c] = fmaf(av, wiZ.comp, aZ[r][c]);            \
    aZ[r][c] = fmaf(hv, whZ.comp, aZ[r][c]);            \
    aI[r][c] = fmaf(av, wiN.comp, aI[r][c]);            \
    aN[r][c] = fmaf(hv, whN.comp, aN[r][c]);

#define GATE_FMA0(c, comp)                              \
    aR[r][c] = fmaf(hv, whR.comp, aR[r][c]);            \
    aZ[r][c] = fmaf(hv, whZ.comp, aZ[r][c]);            \
    aN[r][c] = fmaf(hv, whN.comp, aN[r][c]);

__device__ __forceinline__ float sigmoidf_(float x) {
    return 1.f / (1.f + expf(-x));
}

// layer 1: IN = g_h0 (this step's layer-0 output), H = g_h1 in/out
__global__ __launch_bounds__(512, 1)
void gru_cell_l1(const float* __restrict__ b_ih, const float* __restrict__ b_hh) {
    const int tid = threadIdx.x;
    const int tx = tid & 31, ty = tid >> 5;
    const int m0 = blockIdx.x * 64;
    const int c0 = tx * 4;

    float aR[4][4] = {}, aZ[4][4] = {}, aI[4][4] = {}, aN[4][4] = {};
    const float* inrow[4];
    float* hrow[4];
#pragma unroll
    for (int r = 0; r < 4; ++r) {
        inrow[r] = g_h0 + (size_t)(m0 + ty * 4 + r) * TH;
        hrow[r]  = g_h1 + (size_t)(m0 + ty * 4 + r) * TH;
    }
    const float* wip = g_WtI1 + c0;
    const float* whp = g_WtH1 + c0;
#pragma unroll 2
    for (int k = 0; k < TH; ++k) {
        float4 wiR = *(const float4*)(wip);
        float4 wiZ = *(const float4*)(wip + 128);
        float4 wiN = *(const float4*)(wip + 256);
        float4 whR = *(const float4*)(whp);
        float4 whZ = *(const float4*)(whp + 128);
        float4 whN = *(const float4*)(whp + 256);
        wip += 384; whp += 384;
#pragma unroll
        for (int r = 0; r < 4; ++r) {
            float av = inrow[r][k];
            float hv = hrow[r][k];
            GATE_FMA(0, x) GATE_FMA(1, y) GATE_FMA(2, z) GATE_FMA(3, w)
        }
    }
#pragma unroll
    for (int r = 0; r < 4; ++r) {
        union { float4 v; float a[4]; } o;
#pragma unroll
        for (int c = 0; c < 4; ++c) {
            int j = c0 + c;
            float rr = sigmoidf_(aR[r][c] + b_ih[j] + b_hh[j]);
            float zz = sigmoidf_(aZ[r][c] + b_ih[TH + j] + b_hh[TH + j]);
            float nn = tanhf(aI[r][c] + b_ih[2 * TH + j] +
                             rr * (aN[r][c] + b_hh[2 * TH + j]));
            float hp = hrow[r][j];
            o.a[c] = (1.f - zz) * nn + zz * hp;
        }
        *(float4*)(hrow[r] + c0) = o.v;
    }
}

// layer 0: input = x[:, t, :] (Din=5), H = g_h0 in/out
__global__ __launch_bounds__(512, 1)
void gru_cell_l0(const float* __restrict__ X, int t,
                 const float* __restrict__ Wih0,
                 const float* __restrict__ b_ih, const float* __restrict__ b_hh) {
    const int tid = threadIdx.x;
    const int tx = tid & 31, ty = tid >> 5;
    const int m0 = blockIdx.x * 64;
    const int c0 = tx * 4;

    float xv[4][Fv];
    float* hrow[4];
#pragma unroll
    for (int r = 0; r < 4; ++r) {
        const float* xr = X + (size_t)(m0 + ty * 4 + r) * (Wv * Fv) + t * Fv;
#pragma unroll
        for (int f = 0; f < Fv; ++f) xv[r][f] = xr[f];
        hrow[r] = g_h0 + (size_t)(m0 + ty * 4 + r) * TH;
    }
    float aR[4][4], aZ[4][4], aI[4][4], aN[4][4];
#pragma unroll
    for (int r = 0; r < 4; ++r) {
#pragma unroll
        for (int c = 0; c < 4; ++c) {
            int j = c0 + c;
            float sR = 0.f, sZ = 0.f, sI = 0.f;
#pragma unroll
            for (int f = 0; f < Fv; ++f) {
                sR = fmaf(xv[r][f], Wih0[j * Fv + f], sR);
                sZ = fmaf(xv[r][f], Wih0[(TH + j) * Fv + f], sZ);
                sI = fmaf(xv[r][f], Wih0[(2 * TH + j) * Fv + f], sI);
            }
            aR[r][c] = sR; aZ[r][c] = sZ; aI[r][c] = sI; aN[r][c] = 0.f;
        }
    }
    const float* whp = g_WtH0 + c0;
#pragma unroll 2
    for (int k = 0; k < TH; ++k) {
        float4 whR = *(const float4*)(whp);
        float4 whZ = *(const float4*)(whp + 128);
        float4 whN = *(const float4*)(whp + 256);
        whp += 384;
#pragma unroll
        for (int r = 0; r < 4; ++r) {
            float hv = hrow[r][k];
            GATE_FMA0(0, x) GATE_FMA0(1, y) GATE_FMA0(2, z) GATE_FMA0(3, w)
        }
    }
#pragma unroll
    for (int r = 0; r < 4; ++r) {
        union { float4 v; float a[4]; } o;
#pragma unroll
        for (int c = 0; c < 4; ++c) {
            int j = c0 + c;
            float rr = sigmoidf_(aR[r][c] + b_ih[j] + b_hh[j]);
            float zz = sigmoidf_(aZ[r][c] + b_ih[TH + j] + b_hh[TH + j]);
            float nn = tanhf(aI[r][c] + b_ih[2 * TH + j] +
                             rr * (aN[r][c] + b_hh[2 * TH + j]));
            float hp = hrow[r][j];
            o.a[c] = (1.f - zz) * nn + zz * hp;
        }
        *(float4*)(hrow[r] + c0) = o.v;
    }
}

// ---------------- node stage 1: LN(h1) -> xp, attention scores -------------
// one warp per node, 8 warps / block
__global__ void node_stage1(const float* __restrict__ ln_g, const float* __restrict__ ln_b,
                            const float* __restrict__ gatW,
                            const float* __restrict__ att_s, const float* __restrict__ att_d) {
    __shared__ float ts[8][TH];
    const int lane = threadIdx.x & 31;
    const int warp = threadIdx.x >> 5;
    const int m = blockIdx.x * 8 + warp;
    const float* hr = g_h1 + (size_t)m * TH;

    float v[4], s = 0.f, sq = 0.f;
#pragma unroll
    for (int i = 0; i < 4; ++i) {
        v[i] = hr[lane + 32 * i];
        s += v[i]; sq += v[i] * v[i];
    }
#pragma unroll
    for (int o = 16; o; o >>= 1) {
        s  += __shfl_xor_sync(0xffffffffu, s, o);
        sq += __shfl_xor_sync(0xffffffffu, sq, o);
    }
    float mu = s * (1.f / TH);
    float var = sq * (1.f / TH) - mu * mu;
    float inv = rsqrtf(var + 1e-5f);
#pragma unroll
    for (int i = 0; i < 4; ++i) {
        int k = lane + 32 * i;
        ts[warp][k] = (v[i] - mu) * inv * ln_g[k] + ln_b[k];
    }
    __syncwarp();
    float x0 = 0.f, x1 = 0.f;
#pragma unroll 4
    for (int k = 0; k < TH; ++k) {
        float tv = ts[warp][k];
        x0 = fmaf(tv, gatW[k * SH + lane], x0);
        x1 = fmaf(tv, gatW[k * SH + lane + 32], x1);
    }
    g_xp[(size_t)m * SH + lane] = x0;
    g_xp[(size_t)m * SH + lane + 32] = x1;

    float ps0 = x0 * att_s[lane],      ps1 = x1 * att_s[lane + 32];
    float pd0 = x0 * att_d[lane],      pd1 = x1 * att_d[lane + 32];
#pragma unroll
    for (int o = 8; o; o >>= 1) {
        ps0 += __shfl_xor_sync(0xffffffffu, ps0, o, 16);
        ps1 += __shfl_xor_sync(0xffffffffu, ps1, o, 16);
        pd0 += __shfl_xor_sync(0xffffffffu, pd0, o, 16);
        pd1 += __shfl_xor_sync(0xffffffffu, pd1, o, 16);
    }
    if ((lane & 15) == 0) {
        int h = lane >> 4;                      // 0 or 1
        g_asrc[m * HEADS + h]     = ps0;
        g_asrc[m * HEADS + 2 + h] = ps1;
        g_adst[m * HEADS + h]     = pd0;
        g_adst[m * HEADS + 2 + h] = pd1;
    }
}

// ---------------- edge pass: accumulate exp-weighted numerator + denom -----
// thread = (edge, head). Softmax max-shift dropped (alphas are O(1); identical math).
// Edge-index buffer decoded per g_ei_is64 flag.
__global__ void edge_kernel(const int* __restrict__ ei32) {
    int idx = blockIdx.x * blockDim.x + threadIdx.x;
    if (idx >= ET * HEADS) return;
    int h = idx & 3;
    int e = idx >> 2;
    int s, d;
    if (e < Bv * EB) {
        int g = e / EB;
        int i = e - g * EB;
        if (g_ei_is64) {
            // little-endian int64: take low word at 2*index
            s = ei32[2 * i]            + g * Nv;
            d = ei32[2 * (EB + i)]     + g * Nv;
        } else {
            s = ei32[i]      + g * Nv;
            d = ei32[EB + i] + g * Nv;
        }
    } else {
        s = d = e - Bv * EB;
    }
    float al = g_asrc[s * HEADS + h] + g_adst[d * HEADS + h];
    al = al > 0.f ? al : 0.2f * al;
    float ex = expf(al);
    atomicAdd(&g_den[d * HEADS + h], ex);
    const float* xr = g_xp + (size_t)s * SH + h * 16;
    float* ar = g_agg + (size_t)d * SH + h * 16;
#pragma unroll
    for (int c = 0; c < 16; ++c) atomicAdd(&ar[c], ex * xr[c]);
}

// ---------------- node stage 2: normalize, LN, leaky, MLP head -------------
__global__ void node_stage2(const float* __restrict__ gat_b,
                            const float* __restrict__ ln_g, const float* __restrict__ ln_b,
                            const float* __restrict__ W1, const float* __restrict__ b1,
                            const float* __restrict__ W2, const float* __restrict__ b2,
                            float* __restrict__ out) {
    __shared__ float ys[8][SH];
    const int lane = threadIdx.x & 31;
    const int warp = threadIdx.x >> 5;
    const int m = blockIdx.x * 8 + warp;

    float s0 = g_agg[(size_t)m * SH + lane]      / g_den[m * HEADS + (lane >> 4)]      + gat_b[lane];
    float s1 = g_agg[(size_t)m * SH + lane + 32] / g_den[m * HEADS + 2 + (lane >> 4)]  + gat_b[lane + 32];

    float s = s0 + s1, sq = s0 * s0 + s1 * s1;
#pragma unroll
    for (int o = 16; o; o >>= 1) {
        s  += __shfl_xor_sync(0xffffffffu, s, o);
        sq += __shfl_xor_sync(0xffffffffu, sq, o);
    }
    float mu = s * (1.f / SH);
    float var = sq * (1.f / SH) - mu * mu;
    float inv = rsqrtf(var + 1e-5f);
    float y0 = (s0 - mu) * inv * ln_g[lane] + ln_b[lane];
    float y1 = (s1 - mu) * inv * ln_g[lane + 32] + ln_b[lane + 32];
    y0 = y0 > 0.f ? y0 : 0.2f * y0;
    y1 = y1 > 0.f ? y1 : 0.2f * y1;
    ys[warp][lane] = y0;
    ys[warp][lane + 32] = y1;
    __syncwarp();

    float acc = b1[lane];
#pragma unroll
    for (int k = 0; k < SH; ++k)
        acc = fmaf(ys[warp][k], W1[k * 32 + lane], acc);
    acc = acc > 0.f ? acc : 0.2f * acc;

    float p = acc * W2[lane];
#pragma unroll
    for (int o = 16; o; o >>= 1)
        p += __shfl_xor_sync(0xffffffffu, p, o);
    if (lane == 0) out[m] = p + b2[0];
}

// ---------------- launch ----------------
extern "C" void kernel_launch(void* const* d_in, const int* in_sizes, int n_in,
                              void* d_out, int out_size) {
    const float* x     = (const float*)d_in[0];
    const int*   ei32  = (const int*)d_in[1];     // int32 OR int64 (auto-detected)
    const float* W_ih0 = (const float*)d_in[2];
    const float* W_hh0 = (const float*)d_in[3];
    const float* b_ih0 = (const float*)d_in[4];
    const float* b_hh0 = (const float*)d_in[5];
    const float* W_ih1 = (const float*)d_in[6];
    const float* W_hh1 = (const float*)d_in[7];
    const float* b_ih1 = (const float*)d_in[8];
    const float* b_hh1 = (const float*)d_in[9];
    const float* ln1_g = (const float*)d_in[10];
    const float* ln1_b = (const float*)d_in[11];
    const float* gat_W = (const float*)d_in[12];
    const float* att_s = (const float*)d_in[13];
    const float* att_d = (const float*)d_in[14];
    const float* gat_b = (const float*)d_in[15];
    const float* ln2_g = (const float*)d_in[16];
    const float* ln2_b = (const float*)d_in[17];
    const float* regW1 = (const float*)d_in[18];
    const float* regb1 = (const float*)d_in[19];
    const float* regW2 = (const float*)d_in[20];
    const float* regb2 = (const float*)d_in[21];
    float* out = (float*)d_out;

    detect_ei_kernel<<<1, 256>>>(ei32);
    prep_kernel<<<(TH * 3 * TH + 255) / 256, 256>>>(W_hh0, W_ih1, W_hh1);
    zero_all_kernel<<<4096, 512>>>();

    const int gru_blocks = Mn / 64;  // 500
    for (int t = 0; t < Wv; ++t) {
        gru_cell_l0<<<gru_blocks, 512>>>(x, t, W_ih0, b_ih0, b_hh0);
        gru_cell_l1<<<gru_blocks, 512>>>(b_ih1, b_hh1);
    }

    node_stage1<<<Mn / 8, 256>>>(ln1_g, ln1_b, gat_W, att_s, att_d);
    edge_kernel<<<(ET * HEADS + 255) / 256, 256>>>(ei32);
    node_stage2<<<Mn / 8, 256>>>(gat_b, ln2_g, ln2_b, regW1, regb1, regW2, regb2, out);
}

// round 3
// speedup vs baseline: 1.0036x; 1.0036x over previous
#include <cuda_runtime.h>
#include <math.h>

// ---------------- problem constants ----------------
constexpr int Bv = 16, Nv = 2000, Wv = 32, Fv = 5;
constexpr int TH = 128, SH = 64, HEADS = 4;
constexpr int Mn = Bv * Nv;              // 32000 nodes
constexpr int EB = 32000;                // base edges per graph
constexpr int ET = Bv * EB + Mn;         // 544000 total edges (incl. self loops)

// ---------------- device scratch (no allocations allowed) ----------------
__device__ float g_h0[(size_t)Mn * TH];
__device__ float g_h1[(size_t)Mn * TH];
__device__ float g_xp[(size_t)Mn * SH];
__device__ float g_asrc[Mn * HEADS];
__device__ float g_adst[Mn * HEADS];
__device__ float g_den[Mn * HEADS];
__device__ float g_agg[(size_t)Mn * SH];
__device__ float g_WtH0[TH * 3 * TH];    // [k=128][j=384], j = gate*128+col
__device__ float g_WtI1[TH * 3 * TH];
__device__ float g_WtH1[TH * 3 * TH];
__device__ int   g_ei_is64;              // edge-index dtype flag

// ---------------- probe: detect int32 vs int64 edge index ----------------
// If buffer is int64 (values < 2000), every odd 32-bit word is 0.
// If int32, odd words are random node ids — all-zero probability ~0.
__global__ void detect_ei_kernel(const int* __restrict__ w) {
    __shared__ int nz;
    if (threadIdx.x == 0) nz = 0;
    __syncthreads();
    // inspect first 2048 words (within bounds for both dtypes: >= 64000 words)
    for (int i = threadIdx.x; i < 2048; i += blockDim.x)
        if ((i & 1) && w[i] != 0) atomicOr(&nz, 1);
    __syncthreads();
    if (threadIdx.x == 0) g_ei_is64 = nz ? 0 : 1;
}

// ---------------- prep: transpose GRU weights to k-major ----------------
__global__ void prep_kernel(const float* __restrict__ Whh0,
                            const float* __restrict__ Wih1,
                            const float* __restrict__ Whh1) {
    int i = blockIdx.x * blockDim.x + threadIdx.x;
    if (i < TH * 3 * TH) {
        int j = i % (3 * TH);
        int k = i / (3 * TH);
        g_WtH0[k * 384 + j] = Whh0[j * TH + k];
        g_WtI1[k * 384 + j] = Wih1[j * TH + k];
        g_WtH1[k * 384 + j] = Whh1[j * TH + k];
    }
}

// ---------------- zero state + accumulators ----------------
__global__ void zero_all_kernel() {
    size_t stride = (size_t)gridDim.x * blockDim.x;
    for (size_t i = (size_t)blockIdx.x * blockDim.x + threadIdx.x;
         i < (size_t)Mn * TH; i += stride) {
        g_h0[i] = 0.f;
        g_h1[i] = 0.f;
        if (i < (size_t)Mn * SH) g_agg[i] = 0.f;
        if (i < (size_t)Mn * HEADS) g_den[i] = 0.f;
    }
}

// ---------------- GRU cell kernels ----------------
// Block = 64 nodes, 512 threads. Thread (ty,tx): rows ty*4..+3, cols tx*4..+3.
// Accumulators: aR,aZ (gi+gh summed), aI (input n-part), aN (hidden n-part).

#define GATE_FMA(c, comp)                               \
    aR[r][c] = fmaf(av, wiR.comp, aR[r][c]);            \
    aR[r][c] = fmaf(hv, whR.comp, aR[r][c]);            \
    aZ[r][c] = fmaf(av, wiZ.comp, aZ[r][c]);            \
    aZ[r][c] = fmaf(hv, whZ.comp, aZ[r][c]);            \
    aI[r][c] = fmaf(av, wiN.comp, aI[r][c]);            \
    aN[r][c] = fmaf(hv, whN.comp, aN[r][c]);

#define GATE_FMA0(c, comp)                              \
    aR[r][c] = fmaf(hv, whR.comp, aR[r][c]);            \
    aZ[r][c] = fmaf(hv, whZ.comp, aZ[r][c]);            \
    aN[r][c] = fmaf(hv, whN.comp, aN[r][c]);

__device__ __forceinline__ float sigmoidf_(float x) {
    return 1.f / (1.f + expf(-x));
}

// layer 1: IN = g_h0 (this step's layer-0 output), H = g_h1 in/out
__global__ __launch_bounds__(512, 1)
void gru_cell_l1(const float* __restrict__ b_ih, const float* __restrict__ b_hh) {
    const int tid = threadIdx.x;
    const int tx = tid & 31, ty = tid >> 5;
    const int m0 = blockIdx.x * 64;
    const int c0 = tx * 4;

    float aR[4][4] = {}, aZ[4][4] = {}, aI[4][4] = {}, aN[4][4] = {};
    const float* inrow[4];
    float* hrow[4];
#pragma unroll
    for (int r = 0; r < 4; ++r) {
        inrow[r] = g_h0 + (size_t)(m0 + ty * 4 + r) * TH;
        hrow[r]  = g_h1 + (size_t)(m0 + ty * 4 + r) * TH;
    }
    const float* wip = g_WtI1 + c0;
    const float* whp = g_WtH1 + c0;
#pragma unroll 2
    for (int k = 0; k < TH; ++k) {
        float4 wiR = *(const float4*)(wip);
        float4 wiZ = *(const float4*)(wip + 128);
        float4 wiN = *(const float4*)(wip + 256);
        float4 whR = *(const float4*)(whp);
        float4 whZ = *(const float4*)(whp + 128);
        float4 whN = *(const float4*)(whp + 256);
        wip += 384; whp += 384;
#pragma unroll
        for (int r = 0; r < 4; ++r) {
            float av = inrow[r][k];
            float hv = hrow[r][k];
            GATE_FMA(0, x) GATE_FMA(1, y) GATE_FMA(2, z) GATE_FMA(3, w)
        }
    }
#pragma unroll
    for (int r = 0; r < 4; ++r) {
        union { float4 v; float a[4]; } o;
#pragma unroll
        for (int c = 0; c < 4; ++c) {
            int j = c0 + c;
            float rr = sigmoidf_(aR[r][c] + b_ih[j] + b_hh[j]);
            float zz = sigmoidf_(aZ[r][c] + b_ih[TH + j] + b_hh[TH + j]);
            float nn = tanhf(aI[r][c] + b_ih[2 * TH + j] +
                             rr * (aN[r][c] + b_hh[2 * TH + j]));
            float hp = hrow[r][j];
            o.a[c] = (1.f - zz) * nn + zz * hp;
        }
        *(float4*)(hrow[r] + c0) = o.v;
    }
}

// layer 0: input = x[:, t, :] (Din=5), H = g_h0 in/out
__global__ __launch_bounds__(512, 1)
void gru_cell_l0(const float* __restrict__ X, int t,
                 const float* __restrict__ Wih0,
                 const float* __restrict__ b_ih, const float* __restrict__ b_hh) {
    const int tid = threadIdx.x;
    const int tx = tid & 31, ty = tid >> 5;
    const int m0 = blockIdx.x * 64;
    const int c0 = tx * 4;

    float xv[4][Fv];
    float* hrow[4];
#pragma unroll
    for (int r = 0; r < 4; ++r) {
        const float* xr = X + (size_t)(m0 + ty * 4 + r) * (Wv * Fv) + t * Fv;
#pragma unroll
        for (int f = 0; f < Fv; ++f) xv[r][f] = xr[f];
        hrow[r] = g_h0 + (size_t)(m0 + ty * 4 + r) * TH;
    }
    float aR[4][4], aZ[4][4], aI[4][4], aN[4][4];
#pragma unroll
    for (int r = 0; r < 4; ++r) {
#pragma unroll
        for (int c = 0; c < 4; ++c) {
            int j = c0 + c;
            float sR = 0.f, sZ = 0.f, sI = 0.f;
#pragma unroll
            for (int f = 0; f < Fv; ++f) {
                sR = fmaf(xv[r][f], Wih0[j * Fv + f], sR);
                sZ = fmaf(xv[r][f], Wih0[(TH + j) * Fv + f], sZ);
                sI = fmaf(xv[r][f], Wih0[(2 * TH + j) * Fv + f], sI);
            }
            aR[r][c] = sR; aZ[r][c] = sZ; aI[r][c] = sI; aN[r][c] = 0.f;
        }
    }
    const float* whp = g_WtH0 + c0;
#pragma unroll 2
    for (int k = 0; k < TH; ++k) {
        float4 whR = *(const float4*)(whp);
        float4 whZ = *(const float4*)(whp + 128);
        float4 whN = *(const float4*)(whp + 256);
        whp += 384;
#pragma unroll
        for (int r = 0; r < 4; ++r) {
            float hv = hrow[r][k];
            GATE_FMA0(0, x) GATE_FMA0(1, y) GATE_FMA0(2, z) GATE_FMA0(3, w)
        }
    }
#pragma unroll
    for (int r = 0; r < 4; ++r) {
        union { float4 v; float a[4]; } o;
#pragma unroll
        for (int c = 0; c < 4; ++c) {
            int j = c0 + c;
            float rr = sigmoidf_(aR[r][c] + b_ih[j] + b_hh[j]);
            float zz = sigmoidf_(aZ[r][c] + b_ih[TH + j] + b_hh[TH + j]);
            float nn = tanhf(aI[r][c] + b_ih[2 * TH + j] +
                             rr * (aN[r][c] + b_hh[2 * TH + j]));
            float hp = hrow[r][j];
            o.a[c] = (1.f - zz) * nn + zz * hp;
        }
        *(float4*)(hrow[r] + c0) = o.v;
    }
}

// ---------------- node stage 1: LN(h1) -> xp, attention scores -------------
// one warp per node, 8 warps / block
__global__ void node_stage1(const float* __restrict__ ln_g, const float* __restrict__ ln_b,
                            const float* __restrict__ gatW,
                            const float* __restrict__ att_s, const float* __restrict__ att_d) {
    __shared__ float ts[8][TH];
    const int lane = threadIdx.x & 31;
    const int warp = threadIdx.x >> 5;
    const int m = blockIdx.x * 8 + warp;
    const float* hr = g_h1 + (size_t)m * TH;

    float v[4], s = 0.f, sq = 0.f;
#pragma unroll
    for (int i = 0; i < 4; ++i) {
        v[i] = hr[lane + 32 * i];
        s += v[i]; sq += v[i] * v[i];
    }
#pragma unroll
    for (int o = 16; o; o >>= 1) {
        s  += __shfl_xor_sync(0xffffffffu, s, o);
        sq += __shfl_xor_sync(0xffffffffu, sq, o);
    }
    float mu = s * (1.f / TH);
    float var = sq * (1.f / TH) - mu * mu;
    float inv = rsqrtf(var + 1e-5f);
#pragma unroll
    for (int i = 0; i < 4; ++i) {
        int k = lane + 32 * i;
        ts[warp][k] = (v[i] - mu) * inv * ln_g[k] + ln_b[k];
    }
    __syncwarp();
    float x0 = 0.f, x1 = 0.f;
#pragma unroll 4
    for (int k = 0; k < TH; ++k) {
        float tv = ts[warp][k];
        x0 = fmaf(tv, gatW[k * SH + lane], x0);
        x1 = fmaf(tv, gatW[k * SH + lane + 32], x1);
    }
    g_xp[(size_t)m * SH + lane] = x0;
    g_xp[(size_t)m * SH + lane + 32] = x1;

    float ps0 = x0 * att_s[lane],      ps1 = x1 * att_s[lane + 32];
    float pd0 = x0 * att_d[lane],      pd1 = x1 * att_d[lane + 32];
#pragma unroll
    for (int o = 8; o; o >>= 1) {
        ps0 += __shfl_xor_sync(0xffffffffu, ps0, o, 16);
        ps1 += __shfl_xor_sync(0xffffffffu, ps1, o, 16);
        pd0 += __shfl_xor_sync(0xffffffffu, pd0, o, 16);
        pd1 += __shfl_xor_sync(0xffffffffu, pd1, o, 16);
    }
    if ((lane & 15) == 0) {
        int h = lane >> 4;                      // 0 or 1
        g_asrc[m * HEADS + h]     = ps0;
        g_asrc[m * HEADS + 2 + h] = ps1;
        g_adst[m * HEADS + h]     = pd0;
        g_adst[m * HEADS + 2 + h] = pd1;
    }
}

// ---------------- edge pass: accumulate exp-weighted numerator + denom -----
// thread = (edge, head). Softmax max-shift dropped (alphas are O(1); identical math).
// Edge-index buffer decoded per g_ei_is64 flag.
__global__ void edge_kernel(const int* __restrict__ ei32) {
    int idx = blockIdx.x * blockDim.x + threadIdx.x;
    if (idx >= ET * HEADS) return;
    int h = idx & 3;
    int e = idx >> 2;
    int s, d;
    if (e < Bv * EB) {
        int g = e / EB;
        int i = e - g * EB;
        if (g_ei_is64) {
            // little-endian int64: take low word at 2*index
            s = ei32[2 * i]            + g * Nv;
            d = ei32[2 * (EB + i)]     + g * Nv;
        } else {
            s = ei32[i]      + g * Nv;
            d = ei32[EB + i] + g * Nv;
        }
    } else {
        s = d = e - Bv * EB;
    }
    float al = g_asrc[s * HEADS + h] + g_adst[d * HEADS + h];
    al = al > 0.f ? al : 0.2f * al;
    float ex = expf(al);
    atomicAdd(&g_den[d * HEADS + h], ex);
    const float* xr = g_xp + (size_t)s * SH + h * 16;
    float* ar = g_agg + (size_t)d * SH + h * 16;
#pragma unroll
    for (int c = 0; c < 16; ++c) atomicAdd(&ar[c], ex * xr[c]);
}

// ---------------- node stage 2: normalize, LN, leaky, MLP head -------------
__global__ void node_stage2(const float* __restrict__ gat_b,
                            const float* __restrict__ ln_g, const float* __restrict__ ln_b,
                            const float* __restrict__ W1, const float* __restrict__ b1,
                            const float* __restrict__ W2, const float* __restrict__ b2,
                            float* __restrict__ out) {
    __shared__ float ys[8][SH];
    const int lane = threadIdx.x & 31;
    const int warp = threadIdx.x >> 5;
    const int m = blockIdx.x * 8 + warp;

    float s0 = g_agg[(size_t)m * SH + lane]      / g_den[m * HEADS + (lane >> 4)]      + gat_b[lane];
    float s1 = g_agg[(size_t)m * SH + lane + 32] / g_den[m * HEADS + 2 + (lane >> 4)]  + gat_b[lane + 32];

    float s = s0 + s1, sq = s0 * s0 + s1 * s1;
#pragma unroll
    for (int o = 16; o; o >>= 1) {
        s  += __shfl_xor_sync(0xffffffffu, s, o);
        sq += __shfl_xor_sync(0xffffffffu, sq, o);
    }
    float mu = s * (1.f / SH);
    float var = sq * (1.f / SH) - mu * mu;
    float inv = rsqrtf(var + 1e-5f);
    float y0 = (s0 - mu) * inv * ln_g[lane] + ln_b[lane];
    float y1 = (s1 - mu) * inv * ln_g[lane + 32] + ln_b[lane + 32];
    y0 = y0 > 0.f ? y0 : 0.2f * y0;
    y1 = y1 > 0.f ? y1 : 0.2f * y1;
    ys[warp][lane] = y0;
    ys[warp][lane + 32] = y1;
    __syncwarp();

    float acc = b1[lane];
#pragma unroll
    for (int k = 0; k < SH; ++k)
        acc = fmaf(ys[warp][k], W1[k * 32 + lane], acc);
    acc = acc > 0.f ? acc : 0.2f * acc;

    float p = acc * W2[lane];
#pragma unroll
    for (int o = 16; o; o >>= 1)
        p += __shfl_xor_sync(0xffffffffu, p, o);
    if (lane == 0) out[m] = p + b2[0];
}

// ---------------- launch ----------------
extern "C" void kernel_launch(void* const* d_in, const int* in_sizes, int n_in,
                              void* d_out, int out_size) {
    const float* x     = (const float*)d_in[0];
    const int*   ei32  = (const int*)d_in[1];     // int32 OR int64 (auto-detected)
    const float* W_ih0 = (const float*)d_in[2];
    const float* W_hh0 = (const float*)d_in[3];
    const float* b_ih0 = (const float*)d_in[4];
    const float* b_hh0 = (const float*)d_in[5];
    const float* W_ih1 = (const float*)d_in[6];
    const float* W_hh1 = (const float*)d_in[7];
    const float* b_ih1 = (const float*)d_in[8];
    const float* b_hh1 = (const float*)d_in[9];
    const float* ln1_g = (const float*)d_in[10];
    const float* ln1_b = (const float*)d_in[11];
    const float* gat_W = (const float*)d_in[12];
    const float* att_s = (const float*)d_in[13];
    const float* att_d = (const float*)d_in[14];
    const float* gat_b = (const float*)d_in[15];
    const float* ln2_g = (const float*)d_in[16];
    const float* ln2_b = (const float*)d_in[17];
    const float* regW1 = (const float*)d_in[18];
    const float* regb1 = (const float*)d_in[19];
    const float* regW2 = (const float*)d_in[20];
    const float* regb2 = (const float*)d_in[21];
    float* out = (float*)d_out;

    detect_ei_kernel<<<1, 256>>>(ei32);
    prep_kernel<<<(TH * 3 * TH + 255) / 256, 256>>>(W_hh0, W_ih1, W_hh1);
    zero_all_kernel<<<4096, 512>>>();

    const int gru_blocks = Mn / 64;  // 500
    for (int t = 0; t < Wv; ++t) {
        gru_cell_l0<<<gru_blocks, 512>>>(x, t, W_ih0, b_ih0, b_hh0);
        gru_cell_l1<<<gru_blocks, 512>>>(b_ih1, b_hh1);
    }

    node_stage1<<<Mn / 8, 256>>>(ln1_g, ln1_b, gat_W, att_s, att_d);
    edge_kernel<<<(ET * HEADS + 255) / 256, 256>>>(ei32);
    node_stage2<<<Mn / 8, 256>>>(gat_b, ln2_g, ln2_b, regW1, regb1, regW2, regb2, out);
}

// round 5
// speedup vs baseline: 1.6067x; 1.6010x over previous
#include <cuda_runtime.h>
#include <cuda_bf16.h>
#include <math.h>
#include <stdint.h>

constexpr int Bv = 16, Nv = 2000, Wv = 32, Fv = 5;
constexpr int TH = 128, SH = 64, HEADS = 4;
constexpr int Mn = Bv * Nv, EB = 32000, ET = Bv * EB + Mn;

// ---------------- device scratch ----------------
__device__ float g_h0A[(size_t)Mn * TH];
__device__ float g_h0B[(size_t)Mn * TH];
__device__ float g_h1A[(size_t)Mn * TH];
__device__ float g_h1B[(size_t)Mn * TH];
__device__ float g_xp[(size_t)Mn * SH];
__device__ float g_asrc[Mn * HEADS];
__device__ float g_adst[Mn * HEADS];
__device__ float g_den[Mn * HEADS];
__device__ float g_agg[(size_t)Mn * SH];
__device__ int   g_ei_is64;
// B fragment packs: [q][chunk][gate][wn][thread][2] as u32 (bf16x2)
constexpr int P1SZ = 4 * 16 * 4 * 4 * 64;   // 65536
constexpr int P0SZ = 4 * 8 * 3 * 4 * 64;    // 24576
__device__ uint32_t g_P1h[P1SZ];
__device__ uint32_t g_P1l[P1SZ];
__device__ uint32_t g_P0h[P0SZ];
__device__ uint32_t g_P0l[P0SZ];

__device__ __forceinline__ float sigf(float x) { return 1.f / (1.f + expf(-x)); }

__device__ __forceinline__ void mma16816(float* c, const uint32_t* a,
                                         uint32_t b0, uint32_t b1) {
    asm volatile(
        "mma.sync.aligned.m16n8k16.row.col.f32.bf16.bf16.f32 "
        "{%0,%1,%2,%3}, {%4,%5,%6,%7}, {%8,%9}, {%0,%1,%2,%3};\n"
        : "+f"(c[0]), "+f"(c[1]), "+f"(c[2]), "+f"(c[3])
        : "r"(a[0]), "r"(a[1]), "r"(a[2]), "r"(a[3]), "r"(b0), "r"(b1));
}

__device__ __forceinline__ uint32_t pack_bf16x2(float f0, float f1,
                                                uint32_t& lo_out) {
    __nv_bfloat16 h0 = __float2bfloat16(f0);
    __nv_bfloat16 h1 = __float2bfloat16(f1);
    __nv_bfloat16 l0 = __float2bfloat16(f0 - __bfloat162float(h0));
    __nv_bfloat16 l1 = __float2bfloat16(f1 - __bfloat162float(h1));
    lo_out = (uint32_t)__bfloat16_as_ushort(l0) |
             ((uint32_t)__bfloat16_as_ushort(l1) << 16);
    return (uint32_t)__bfloat16_as_ushort(h0) |
           ((uint32_t)__bfloat16_as_ushort(h1) << 16);
}

// ---------------- edge-index dtype probe ----------------
__global__ void detect_ei_kernel(const int* __restrict__ w) {
    __shared__ int nz;
    if (threadIdx.x == 0) nz = 0;
    __syncthreads();
    for (int i = threadIdx.x; i < 2048; i += blockDim.x)
        if ((i & 1) && w[i] != 0) atomicOr(&nz, 1);
    __syncthreads();
    if (threadIdx.x == 0) g_ei_is64 = nz ? 0 : 1;
}

// ---------------- prep: pack weights into MMA fragment order ----------------
__global__ void prep_pack(const float* __restrict__ Wih1,
                          const float* __restrict__ Whh1,
                          const float* __restrict__ Whh0) {
    int idx = blockIdx.x * blockDim.x + threadIdx.x;
    if (idx < P1SZ) {
        int tr = idx & 63, t = tr >> 1, r = tr & 1;
        int wn = (idx >> 6) & 3, gate = (idx >> 8) & 3;
        int ch = (idx >> 10) & 15, q = idx >> 14;
        int j = q * 32 + wn * 8 + (t >> 2);
        int k0 = ch * 16 + (t & 3) * 2 + r * 8;
        float v0 = 0.f, v1 = 0.f;
        if (k0 < 128) {
            if (gate < 3) {
                const float* Wr = Wih1 + (size_t)(gate * 128 + j) * 128;
                v0 = Wr[k0]; v1 = Wr[k0 + 1];
            }
        } else {
            if (gate != 2) {
                int gr = (gate == 3) ? 2 : gate;
                const float* Wr = Whh1 + (size_t)(gr * 128 + j) * 128;
                v0 = Wr[k0 - 128]; v1 = Wr[k0 - 127];
            }
        }
        uint32_t lo;
        uint32_t hi = pack_bf16x2(v0, v1, lo);
        g_P1h[idx] = hi; g_P1l[idx] = lo;
    } else if (idx < P1SZ + P0SZ) {
        int i0 = idx - P1SZ;
        int tr = i0 & 63, t = tr >> 1, r = tr & 1;
        int rest = i0 >> 6;
        int wn = rest & 3; rest >>= 2;
        int gate = rest % 3; rest /= 3;
        int ch = rest & 7, q = rest >> 3;
        int j = q * 32 + wn * 8 + (t >> 2);
        int k0 = ch * 16 + (t & 3) * 2 + r * 8;
        const float* Wr = Whh0 + (size_t)(gate * 128 + j) * 128;
        uint32_t lo;
        uint32_t hi = pack_bf16x2(Wr[k0], Wr[k0 + 1], lo);
        g_P0h[i0] = hi; g_P0l[i0] = lo;
    }
}

__global__ void zero_all_kernel() {
    size_t stride = (size_t)gridDim.x * blockDim.x;
    for (size_t i = (size_t)blockIdx.x * blockDim.x + threadIdx.x;
         i < (size_t)Mn * TH; i += stride) {
        g_h0A[i] = 0.f;
        g_h1A[i] = 0.f;
        if (i < (size_t)Mn * SH) g_agg[i] = 0.f;
        if (i < (size_t)Mn * HEADS) g_den[i] = 0.f;
    }
}

// ===== GRU step via mma.sync split-bf16. grid (250, 4), 512 threads =====
template <int LAYER>
__global__ __launch_bounds__(512, 1)
void gru_step(int t, const float* __restrict__ X, const float* __restrict__ Wih0,
              const float* __restrict__ b_ih, const float* __restrict__ b_hh) {
    constexpr int KF  = LAYER ? 256 : 128;
    constexpr int NCH = KF / 16;
    constexpr int NG  = LAYER ? 4 : 3;

    const float* h0in  = (t & 1) ? g_h0B : g_h0A;
    float*       h0out = (t & 1) ? g_h0A : g_h0B;
    const float* h1in  = (t & 1) ? g_h1B : g_h1A;
    float*       h1out = (t & 1) ? g_h1A : g_h1B;
    const float* src0 = LAYER ? h0out : h0in;
    const float* src1 = h1in;
    const float* hold = LAYER ? h1in : h0in;
    float*       hout = LAYER ? h1out : h0out;

    extern __shared__ char smem[];  // [hi: NCH*4096][lo: NCH*4096]
    char* shi = smem;
    char* slo = smem + NCH * 4096;

    const int tid = threadIdx.x, lane = tid & 31, wid = tid >> 5;
    const int wm = wid >> 2, wn = wid & 3;
    const int m0 = blockIdx.x * 128, q = blockIdx.y;

    // ---- A convert: fp32 -> bf16 hi/lo, chunk-blocked + XOR swizzle ----
    {
        const int row = tid >> 2, kq = tid & 3, span = KF / 4;
        const float* sA = src0 + (size_t)(m0 + row) * TH;
        const float* sB = src1 + (size_t)(m0 + row) * TH;
        const int rsw = row & 7;
#pragma unroll
        for (int k = kq * span; k < kq * span + span; k += 2) {
            float f0, f1;
            if (LAYER && k >= 128) {
                float2 v = *(const float2*)(sB + k - 128);
                f0 = v.x; f1 = v.y;
            } else {
                float2 v = *(const float2*)(sA + k);
                f0 = v.x; f1 = v.y;
            }
            uint32_t lo;
            uint32_t hi = pack_bf16x2(f0, f1, lo);
            int p = (k & 15) >> 1;
            int off = (k >> 4) * 4096 + row * 32 + ((p ^ rsw) << 2);
            *(uint32_t*)(shi + off) = hi;
            *(uint32_t*)(slo + off) = lo;
        }
    }
    __syncthreads();

    float acc[NG][2][4];
#pragma unroll
    for (int g = 0; g < NG; ++g)
#pragma unroll
        for (int mi = 0; mi < 2; ++mi)
#pragma unroll
            for (int r = 0; r < 4; ++r) acc[g][mi][r] = 0.f;

    const int gr = lane >> 2, pc = lane & 3;
    const int pA0 = (pc ^ gr) << 2;
    const int rb0 = (wm * 32 + gr) * 32;

    const uint32_t* Ph = LAYER ? g_P1h : g_P0h;
    const uint32_t* Pl = LAYER ? g_P1l : g_P0l;

#pragma unroll 2
    for (int ch = 0; ch < NCH; ++ch) {
        const int cb = ch * 4096;
        uint32_t ah[2][4], al[2][4];
#pragma unroll
        for (int mi = 0; mi < 2; ++mi) {
            int b = cb + rb0 + mi * 512;
            ah[mi][0] = *(const uint32_t*)(shi + b + pA0);
            ah[mi][1] = *(const uint32_t*)(shi + b + 256 + pA0);
            ah[mi][2] = *(const uint32_t*)(shi + b + (pA0 ^ 16));
            ah[mi][3] = *(const uint32_t*)(shi + b + 256 + (pA0 ^ 16));
            al[mi][0] = *(const uint32_t*)(slo + b + pA0);
            al[mi][1] = *(const uint32_t*)(slo + b + 256 + pA0);
            al[mi][2] = *(const uint32_t*)(slo + b + (pA0 ^ 16));
            al[mi][3] = *(const uint32_t*)(slo + b + 256 + (pA0 ^ 16));
        }
#pragma unroll
        for (int g = 0; g < NG; ++g) {
            if (LAYER) {                       // I: chunks 0-7 only; N: 8-15 only
                if (ch < 8 ? (g == 3) : (g == 2)) continue;
            }
            int bidx = ((((q * NCH + ch) * NG + g) * 4 + wn) << 6) + (lane << 1);
            uint2 bh = *(const uint2*)(Ph + bidx);
            uint2 bl = *(const uint2*)(Pl + bidx);
#pragma unroll
            for (int mi = 0; mi < 2; ++mi) {
                mma16816(acc[g][mi], ah[mi], bh.x, bh.y);
                mma16816(acc[g][mi], al[mi], bh.x, bh.y);
                mma16816(acc[g][mi], ah[mi], bl.x, bl.y);
            }
        }
    }

    // ---- epilogue: fused gates + h update, all in registers ----
    const int jb = q * 32 + wn * 8 + pc * 2;
    float br[2], bz[2], bi[2], bn[2];
#pragma unroll
    for (int e = 0; e < 2; ++e) {
        br[e] = b_ih[jb + e] + b_hh[jb + e];
        bz[e] = b_ih[128 + jb + e] + b_hh[128 + jb + e];
        bi[e] = b_ih[256 + jb + e];
        bn[e] = b_hh[256 + jb + e];
    }
    float wxr[2][Fv], wxz[2][Fv], wxi[2][Fv];
    if (!LAYER) {
#pragma unroll
        for (int e = 0; e < 2; ++e)
#pragma unroll
            for (int f = 0; f < Fv; ++f) {
                wxr[e][f] = Wih0[(jb + e) * Fv + f];
                wxz[e][f] = Wih0[(128 + jb + e) * Fv + f];
                wxi[e][f] = Wih0[(256 + jb + e) * Fv + f];
            }
    }
#pragma unroll
    for (int mi = 0; mi < 2; ++mi) {
#pragma unroll
        for (int half = 0; half < 2; ++half) {
            const int m = m0 + wm * 32 + mi * 16 + gr + half * 8;
            const int ro = half * 2;
            float xv[Fv];
            if (!LAYER) {
                const float* xr = X + ((size_t)m * Wv + t) * Fv;
#pragma unroll
                for (int f = 0; f < Fv; ++f) xv[f] = xr[f];
            }
            float2 hpv = *(const float2*)(hold + (size_t)m * TH + jb);
            float h2[2];
#pragma unroll
            for (int e = 0; e < 2; ++e) {
                float R = acc[0][mi][ro + e];
                float Z = acc[1][mi][ro + e];
                float I, N;
                if (LAYER) {
                    I = acc[2][mi][ro + e];
                    N = acc[3][mi][ro + e];
                } else {
                    N = acc[2][mi][ro + e];
                    float sR = 0.f, sZ = 0.f, sI = 0.f;
#pragma unroll
                    for (int f = 0; f < Fv; ++f) {
                        sR = fmaf(xv[f], wxr[e][f], sR);
                        sZ = fmaf(xv[f], wxz[e][f], sZ);
                        sI = fmaf(xv[f], wxi[e][f], sI);
                    }
                    R += sR; Z += sZ; I = sI;
                }
                float rr = sigf(R + br[e]);
                float zz = sigf(Z + bz[e]);
                float nn = tanhf(I + bi[e] + rr * (N + bn[e]));
                float hp = e ? hpv.y : hpv.x;
                h2[e] = (1.f - zz) * nn + zz * hp;
            }
            *(float2*)(hout + (size_t)m * TH + jb) = make_float2(h2[0], h2[1]);
        }
    }
}

// ---- node stage 1: LN(h1) -> xp, attention scores ----
__global__ void node_stage1(const float* __restrict__ ln_g, const float* __restrict__ ln_b,
                            const float* __restrict__ gatW,
                            const float* __restrict__ att_s, const float* __restrict__ att_d) {
    __shared__ float ts[8][TH];
    const int lane = threadIdx.x & 31, warp = threadIdx.x >> 5;
    const int m = blockIdx.x * 8 + warp;
    const float* hr = g_h1A + (size_t)m * TH;   // t=31 (odd) writes A
    float v[4], s = 0.f, sq = 0.f;
#pragma unroll
    for (int i = 0; i < 4; ++i) { v[i] = hr[lane + 32 * i]; s += v[i]; sq += v[i] * v[i]; }
#pragma unroll
    for (int o = 16; o; o >>= 1) {
        s  += __shfl_xor_sync(0xffffffffu, s, o);
        sq += __shfl_xor_sync(0xffffffffu, sq, o);
    }
    float mu = s * (1.f / TH), var = sq * (1.f / TH) - mu * mu, inv = rsqrtf(var + 1e-5f);
#pragma unroll
    for (int i = 0; i < 4; ++i) {
        int k = lane + 32 * i;
        ts[warp][k] = (v[i] - mu) * inv * ln_g[k] + ln_b[k];
    }
    __syncwarp();
    float x0 = 0.f, x1 = 0.f;
#pragma unroll 4
    for (int k = 0; k < TH; ++k) {
        float tv = ts[warp][k];
        x0 = fmaf(tv, gatW[k * SH + lane], x0);
        x1 = fmaf(tv, gatW[k * SH + lane + 32], x1);
    }
    g_xp[(size_t)m * SH + lane] = x0;
    g_xp[(size_t)m * SH + lane + 32] = x1;
    float ps0 = x0 * att_s[lane], ps1 = x1 * att_s[lane + 32];
    float pd0 = x0 * att_d[lane], pd1 = x1 * att_d[lane + 32];
#pragma unroll
    for (int o = 8; o; o >>= 1) {
        ps0 += __shfl_xor_sync(0xffffffffu, ps0, o, 16);
        ps1 += __shfl_xor_sync(0xffffffffu, ps1, o, 16);
        pd0 += __shfl_xor_sync(0xffffffffu, pd0, o, 16);
        pd1 += __shfl_xor_sync(0xffffffffu, pd1, o, 16);
    }
    if ((lane & 15) == 0) {
        int h = lane >> 4;
        g_asrc[m * HEADS + h] = ps0;  g_asrc[m * HEADS + 2 + h] = ps1;
        g_adst[m * HEADS + h] = pd0;  g_adst[m * HEADS + 2 + h] = pd1;
    }
}

// ---- edge pass ----
__global__ void edge_kernel(const int* __restrict__ ei32) {
    int idx = blockIdx.x * blockDim.x + threadIdx.x;
    if (idx >= ET * HEADS) return;
    int h = idx & 3, e = idx >> 2, s, d;
    if (e < Bv * EB) {
        int g = e / EB, i = e - g * EB;
        if (g_ei_is64) { s = ei32[2 * i] + g * Nv; d = ei32[2 * (EB + i)] + g * Nv; }
        else           { s = ei32[i] + g * Nv;     d = ei32[EB + i] + g * Nv; }
    } else s = d = e - Bv * EB;
    float al = g_asrc[s * HEADS + h] + g_adst[d * HEADS + h];
    al = al > 0.f ? al : 0.2f * al;
    float ex = expf(al);
    atomicAdd(&g_den[d * HEADS + h], ex);
    const float* xr = g_xp + (size_t)s * SH + h * 16;
    float* ar = g_agg + (size_t)d * SH + h * 16;
#pragma unroll
    for (int c = 0; c < 16; ++c) atomicAdd(&ar[c], ex * xr[c]);
}

// ---- node stage 2 ----
__global__ void node_stage2(const float* __restrict__ gat_b,
                            const float* __restrict__ ln_g, const float* __restrict__ ln_b,
                            const float* __restrict__ W1, const float* __restrict__ b1,
                            const float* __restrict__ W2, const float* __restrict__ b2,
                            float* __restrict__ out) {
    __shared__ float ys[8][SH];
    const int lane = threadIdx.x & 31, warp = threadIdx.x >> 5;
    const int m = blockIdx.x * 8 + warp;
    float s0 = g_agg[(size_t)m * SH + lane]      / g_den[m * HEADS + (lane >> 4)]     + gat_b[lane];
    float s1 = g_agg[(size_t)m * SH + lane + 32] / g_den[m * HEADS + 2 + (lane >> 4)] + gat_b[lane + 32];
    float s = s0 + s1, sq = s0 * s0 + s1 * s1;
#pragma unroll
    for (int o = 16; o; o >>= 1) {
        s  += __shfl_xor_sync(0xffffffffu, s, o);
        sq += __shfl_xor_sync(0xffffffffu, sq, o);
    }
    float mu = s * (1.f / SH), var = sq * (1.f / SH) - mu * mu, inv = rsqrtf(var + 1e-5f);
    float y0 = (s0 - mu) * inv * ln_g[lane] + ln_b[lane];
    float y1 = (s1 - mu) * inv * ln_g[lane + 32] + ln_b[lane + 32];
    y0 = y0 > 0.f ? y0 : 0.2f * y0;
    y1 = y1 > 0.f ? y1 : 0.2f * y1;
    ys[warp][lane] = y0; ys[warp][lane + 32] = y1;
    __syncwarp();
    float acc = b1[lane];
#pragma unroll
    for (int k = 0; k < SH; ++k) acc = fmaf(ys[warp][k], W1[k * 32 + lane], acc);
    acc = acc > 0.f ? acc : 0.2f * acc;
    float p = acc * W2[lane];
#pragma unroll
    for (int o = 16; o; o >>= 1) p += __shfl_xor_sync(0xffffffffu, p, o);
    if (lane == 0) out[m] = p + b2[0];
}

extern "C" void kernel_launch(void* const* d_in, const int* in_sizes, int n_in,
                              void* d_out, int out_size) {
    const float* x     = (const float*)d_in[0];
    const int*   ei32  = (const int*)d_in[1];
    const float* W_ih0 = (const float*)d_in[2];
    const float* W_hh0 = (const float*)d_in[3];
    const float* b_ih0 = (const float*)d_in[4];
    const float* b_hh0 = (const float*)d_in[5];
    const float* W_ih1 = (const float*)d_in[6];
    const float* W_hh1 = (const float*)d_in[7];
    const float* b_ih1 = (const float*)d_in[8];
    const float* b_hh1 = (const float*)d_in[9];
    const float* ln1_g = (const float*)d_in[10];
    const float* ln1_b = (const float*)d_in[11];
    const float* gat_W = (const float*)d_in[12];
    const float* att_s = (const float*)d_in[13];
    const float* att_d = (const float*)d_in[14];
    const float* gat_b = (const float*)d_in[15];
    const float* ln2_g = (const float*)d_in[16];
    const float* ln2_b = (const float*)d_in[17];
    const float* regW1 = (const float*)d_in[18];
    const float* regb1 = (const float*)d_in[19];
    const float* regW2 = (const float*)d_in[20];
    const float* regb2 = (const float*)d_in[21];
    float* out = (float*)d_out;

    const int SMEM0 = 8 * 4096 * 2;    // 64 KB
    const int SMEM1 = 16 * 4096 * 2;   // 128 KB
    cudaFuncSetAttribute(gru_step<0>, cudaFuncAttributeMaxDynamicSharedMemorySize, SMEM0);
    cudaFuncSetAttribute(gru_step<1>, cudaFuncAttributeMaxDynamicSharedMemorySize, SMEM1);

    detect_ei_kernel<<<1, 256>>>(ei32);
    prep_pack<<<(P1SZ + P0SZ + 255) / 256, 256>>>(W_ih1, W_hh1, W_hh0);
    zero_all_kernel<<<4096, 512>>>();

    dim3 grid(250, 4);
    for (int t = 0; t < Wv; ++t) {
        gru_step<0><<<grid, 512, SMEM0>>>(t, x, W_ih0, b_ih0, b_hh0);
        gru_step<1><<<grid, 512, SMEM1>>>(t, x, W_ih0, b_ih1, b_hh1);
    }

    node_stage1<<<Mn / 8, 256>>>(ln1_g, ln1_b, gat_W, att_s, att_d);
    edge_kernel<<<(ET * HEADS + 255) / 256, 256>>>(ei32);
    node_stage2<<<Mn / 8, 256>>>(gat_b, ln2_g, ln2_b, regW1, regb1, regW2, regb2, out);
}

// round 7
// speedup vs baseline: 3.3421x; 2.0801x over previous
#include <cuda_runtime.h>
#include <cuda_bf16.h>
#include <math.h>
#include <stdint.h>

constexpr int Bv = 16, Nv = 2000, Wv = 32, Fv = 5;
constexpr int TH = 128, SH = 64, HEADS = 4;
constexpr int Mn = Bv * Nv, EB = 32000, ET = Bv * EB + Mn;

// ---------------- device scratch ----------------
__device__ float g_h1[(size_t)Mn * TH];
__device__ float g_xp[(size_t)Mn * SH];
__device__ float g_asrc[Mn * HEADS];
__device__ float g_adst[Mn * HEADS];
__device__ float g_den[Mn * HEADS];
__device__ float g_agg[(size_t)Mn * SH];
__device__ int   g_ei_is64;
// B packs: uint4 = (bh_r0, bh_r1, bl_r0, bl_r1) per (ch, gate, jslot, lane)
constexpr int Q1N = 16 * 4 * 16 * 32;   // 32768
constexpr int Q0N = 8 * 3 * 16 * 32;    // 12288
__device__ uint4 g_Q1[Q1N];
__device__ uint4 g_Q0[Q0N];

__device__ __forceinline__ float sigf(float x) { return 1.f / (1.f + expf(-x)); }

__device__ __forceinline__ void mma16816(float* c, const uint32_t* a,
                                         uint32_t b0, uint32_t b1) {
    asm volatile(
        "mma.sync.aligned.m16n8k16.row.col.f32.bf16.bf16.f32 "
        "{%0,%1,%2,%3}, {%4,%5,%6,%7}, {%8,%9}, {%0,%1,%2,%3};\n"
        : "+f"(c[0]), "+f"(c[1]), "+f"(c[2]), "+f"(c[3])
        : "r"(a[0]), "r"(a[1]), "r"(a[2]), "r"(a[3]), "r"(b0), "r"(b1));
}

__device__ __forceinline__ uint32_t pack_bf16x2(float f0, float f1, uint32_t& lo_out) {
    __nv_bfloat16 h0 = __float2bfloat16(f0);
    __nv_bfloat16 h1 = __float2bfloat16(f1);
    __nv_bfloat16 l0 = __float2bfloat16(f0 - __bfloat162float(h0));
    __nv_bfloat16 l1 = __float2bfloat16(f1 - __bfloat162float(h1));
    lo_out = (uint32_t)__bfloat16_as_ushort(l0) | ((uint32_t)__bfloat16_as_ushort(l1) << 16);
    return (uint32_t)__bfloat16_as_ushort(h0) | ((uint32_t)__bfloat16_as_ushort(h1) << 16);
}
__device__ __forceinline__ float bf_lo(uint32_t w) {
    return __bfloat162float(__ushort_as_bfloat16((unsigned short)(w & 0xffff)));
}
__device__ __forceinline__ float bf_hi(uint32_t w) {
    return __bfloat162float(__ushort_as_bfloat16((unsigned short)(w >> 16)));
}

// ---------------- edge-index dtype probe ----------------
__global__ void detect_ei_kernel(const int* __restrict__ w) {
    __shared__ int nz;
    if (threadIdx.x == 0) nz = 0;
    __syncthreads();
    for (int i = threadIdx.x; i < 2048; i += blockDim.x)
        if ((i & 1) && w[i] != 0) atomicOr(&nz, 1);
    __syncthreads();
    if (threadIdx.x == 0) g_ei_is64 = nz ? 0 : 1;
}

// ---------------- prep: pack weights into uint4 MMA fragments ----------------
__global__ void prep_pack(const float* __restrict__ Wih1,
                          const float* __restrict__ Whh1,
                          const float* __restrict__ Whh0) {
    int idx = blockIdx.x * blockDim.x + threadIdx.x;
    if (idx < Q1N) {
        int lane = idx & 31, js = (idx >> 5) & 15, g = (idx >> 9) & 3, ch = idx >> 11;
        int j = js * 8 + (lane >> 2);
        float v[2][2];   // [r][elem]
#pragma unroll
        for (int r = 0; r < 2; ++r) {
            int k0 = ch * 16 + (lane & 3) * 2 + r * 8;
            float a = 0.f, b = 0.f;
            if (ch < 8) {
                if (g < 3) {
                    const float* Wr = Wih1 + (size_t)(g * 128 + j) * 128;
                    a = Wr[k0]; b = Wr[k0 + 1];
                }
            } else {
                int km = k0 - 128;
                if (g != 2) {
                    int gg = (g == 3) ? 2 : g;
                    const float* Wr = Whh1 + (size_t)(gg * 128 + j) * 128;
                    a = Wr[km]; b = Wr[km + 1];
                }
            }
            v[r][0] = a; v[r][1] = b;
        }
        uint4 o;
        uint32_t lo0, lo1;
        o.x = pack_bf16x2(v[0][0], v[0][1], lo0);
        o.y = pack_bf16x2(v[1][0], v[1][1], lo1);
        o.z = lo0; o.w = lo1;
        g_Q1[idx] = o;
    } else if (idx < Q1N + Q0N) {
        int i0 = idx - Q1N;
        int lane = i0 & 31, js = (i0 >> 5) & 15;
        int rest = i0 >> 9;
        int g = rest % 3, ch = rest / 3;
        int j = js * 8 + (lane >> 2);
        const float* Wr = Whh0 + (size_t)(g * 128 + j) * 128;
        uint4 o;
        uint32_t lo0, lo1;
        int k0 = ch * 16 + (lane & 3) * 2;
        o.x = pack_bf16x2(Wr[k0], Wr[k0 + 1], lo0);
        o.y = pack_bf16x2(Wr[k0 + 8], Wr[k0 + 9], lo1);
        o.z = lo0; o.w = lo1;
        g_Q0[i0] = o;
    }
}

__global__ void zero_kernel() {
    size_t stride = (size_t)gridDim.x * blockDim.x;
    for (size_t i = (size_t)blockIdx.x * blockDim.x + threadIdx.x;
         i < (size_t)Mn * SH; i += stride) {
        g_agg[i] = 0.f;
        if (i < (size_t)Mn * HEADS) g_den[i] = 0.f;
    }
}

// ---------------- helpers for the persistent GRU kernel ----------------
__device__ __forceinline__ void load_afrag(const char* shi, const char* slo,
                                           int cb, int rb0, int pA0,
                                           uint32_t ah[2][4], uint32_t al[2][4]) {
#pragma unroll
    for (int mi = 0; mi < 2; ++mi) {
        int b = cb + rb0 + mi * 512;
        ah[mi][0] = *(const uint32_t*)(shi + b + pA0);
        ah[mi][1] = *(const uint32_t*)(shi + b + 256 + pA0);
        ah[mi][2] = *(const uint32_t*)(shi + b + (pA0 ^ 16));
        ah[mi][3] = *(const uint32_t*)(shi + b + 256 + (pA0 ^ 16));
        al[mi][0] = *(const uint32_t*)(slo + b + pA0);
        al[mi][1] = *(const uint32_t*)(slo + b + 256 + pA0);
        al[mi][2] = *(const uint32_t*)(slo + b + (pA0 ^ 16));
        al[mi][3] = *(const uint32_t*)(slo + b + 256 + (pA0 ^ 16));
    }
}

#define MMA3(accp, ahv, alv, bq)              \
    mma16816(accp, ahv, (bq).x, (bq).y);      \
    mma16816(accp, alv, (bq).x, (bq).y);      \
    mma16816(accp, ahv, (bq).z, (bq).w);

// ===== persistent GRU: grid 250, block 512 (16 warps) =====
__global__ __launch_bounds__(512, 1)
void gru_all(const float* __restrict__ X, const float* __restrict__ Wih0,
             const float* __restrict__ bi0, const float* __restrict__ bh0,
             const float* __restrict__ bi1, const float* __restrict__ bh1) {
    extern __shared__ char sm[];
    char* shi = sm;                          // 16 chunks * 4KB = 64KB (bf16 hi)
    char* slo = sm + 65536;                  // 64KB (bf16 lo)
    float* sW = (float*)(sm + 131072);       // Wih0: 1920 floats
    float* sb = (float*)(sm + 131072 + 7680);// biases: [L][4][128] = 1024 floats

    const int tid = threadIdx.x, lane = tid & 31, wid = tid >> 5;
    const int wm = wid >> 2, wn = wid & 3, gr = lane >> 2, pc = lane & 3;
    const int m0 = blockIdx.x * 128;
    const int rb0 = (wm * 32 + gr) * 32;
    const int pA0 = (pc ^ gr) << 2;

    // init: zero state (16384 words per 64KB buffer!), copy Wih0, biases
    for (int i = tid; i < 16384; i += 512) {
        ((uint32_t*)shi)[i] = 0;
        ((uint32_t*)slo)[i] = 0;
    }
    for (int i = tid; i < 384 * Fv; i += 512) sW[i] = Wih0[i];
    for (int i = tid; i < 1024; i += 512) {
        int j = i & 127, which = (i >> 7) & 3, L = i >> 9;
        const float* BI = L ? bi1 : bi0;
        const float* BH = L ? bh1 : bh0;
        float v;
        if (which == 0)      v = BI[j] + BH[j];
        else if (which == 1) v = BI[128 + j] + BH[128 + j];
        else if (which == 2) v = BI[256 + j];
        else                 v = BH[256 + j];
        sb[i] = v;
    }
    __syncthreads();

    for (int t = 0; t < Wv; ++t) {
        uint32_t hHi[2][8], hLo[2][8];

        // ================= LAYER 0 =================
        for (int p = 0; p < 2; ++p) {
            float acc[3][2][2][4];
#pragma unroll
            for (int g = 0; g < 3; ++g)
#pragma unroll
                for (int nt = 0; nt < 2; ++nt)
#pragma unroll
                    for (int mi = 0; mi < 2; ++mi)
#pragma unroll
                        for (int e = 0; e < 4; ++e) acc[g][nt][mi][e] = 0.f;
            const int js0 = p * 8 + wn * 2;
#pragma unroll 2
            for (int ch = 0; ch < 8; ++ch) {
                uint32_t ah[2][4], al[2][4];
                load_afrag(shi, slo, ch * 4096, rb0, pA0, ah, al);
#pragma unroll
                for (int g = 0; g < 3; ++g)
#pragma unroll
                    for (int nt = 0; nt < 2; ++nt) {
                        uint4 b = g_Q0[((ch * 3 + g) * 16 + js0 + nt) * 32 + lane];
#pragma unroll
                        for (int mi = 0; mi < 2; ++mi) { MMA3(acc[g][nt][mi], ah[mi], al[mi], b); }
                    }
            }
            // epilogue L0 (pass p)
#pragma unroll
            for (int mi = 0; mi < 2; ++mi)
#pragma unroll
                for (int half = 0; half < 2; ++half) {
                    const int r = wm * 32 + mi * 16 + gr + half * 8;
                    const int m = m0 + r;
                    float xv[Fv];
                    const float* xr = X + ((size_t)m * Wv + t) * Fv;
#pragma unroll
                    for (int f = 0; f < Fv; ++f) xv[f] = xr[f];
#pragma unroll
                    for (int nt = 0; nt < 2; ++nt) {
                        const int jb = p * 64 + wn * 16 + nt * 8 + pc * 2;
                        const int wq = nt * 4 + pc;
                        const int off = (p * 4 + wn) * 4096 + r * 32 + ((wq ^ (r & 7)) << 2);
                        uint32_t phi = *(const uint32_t*)(shi + off);
                        uint32_t plo = *(const uint32_t*)(slo + off);
                        float hp[2] = { bf_lo(phi) + bf_lo(plo), bf_hi(phi) + bf_hi(plo) };
                        float h2[2];
#pragma unroll
                        for (int e = 0; e < 2; ++e) {
                            int j = jb + e;
                            float sR = 0.f, sZ = 0.f, sI = 0.f;
#pragma unroll
                            for (int f = 0; f < Fv; ++f) {
                                sR = fmaf(xv[f], sW[j * Fv + f], sR);
                                sZ = fmaf(xv[f], sW[(128 + j) * Fv + f], sZ);
                                sI = fmaf(xv[f], sW[(256 + j) * Fv + f], sI);
                            }
                            int c = half * 2 + e;
                            float rr = sigf(acc[0][nt][mi][c] + sR + sb[j]);
                            float zz = sigf(acc[1][nt][mi][c] + sZ + sb[128 + j]);
                            float nn = tanhf(sI + sb[256 + j] +
                                             rr * (acc[2][nt][mi][c] + sb[384 + j]));
                            h2[e] = (1.f - zz) * nn + zz * hp[e];
                        }
                        int hidx = (nt * 2 + mi) * 2 + half;
                        hHi[p][hidx] = pack_bf16x2(h2[0], h2[1], hLo[p][hidx]);
                    }
                }
        }
        __syncthreads();
        // write h0 (chunks 0..7)
#pragma unroll
        for (int p = 0; p < 2; ++p)
#pragma unroll
            for (int nt = 0; nt < 2; ++nt)
#pragma unroll
                for (int mi = 0; mi < 2; ++mi)
#pragma unroll
                    for (int half = 0; half < 2; ++half) {
                        const int r = wm * 32 + mi * 16 + gr + half * 8;
                        const int wq = nt * 4 + pc;
                        const int off = (p * 4 + wn) * 4096 + r * 32 + ((wq ^ (r & 7)) << 2);
                        int hidx = (nt * 2 + mi) * 2 + half;
                        *(uint32_t*)(shi + off) = hHi[p][hidx];
                        *(uint32_t*)(slo + off) = hLo[p][hidx];
                    }
        __syncthreads();

        // ================= LAYER 1 =================
        for (int p = 0; p < 2; ++p) {
            float acc[4][2][2][4];
#pragma unroll
            for (int g = 0; g < 4; ++g)
#pragma unroll
                for (int nt = 0; nt < 2; ++nt)
#pragma unroll
                    for (int mi = 0; mi < 2; ++mi)
#pragma unroll
                        for (int e = 0; e < 4; ++e) acc[g][nt][mi][e] = 0.f;
            const int js0 = p * 8 + wn * 2;
#pragma unroll 2
            for (int ch = 0; ch < 8; ++ch) {           // K 0..127 (h0): R,Z,I
                uint32_t ah[2][4], al[2][4];
                load_afrag(shi, slo, ch * 4096, rb0, pA0, ah, al);
                const int gl[3] = {0, 1, 2};
#pragma unroll
                for (int gi = 0; gi < 3; ++gi) {
                    const int g = gl[gi];
#pragma unroll
                    for (int nt = 0; nt < 2; ++nt) {
                        uint4 b = g_Q1[((ch * 4 + g) * 16 + js0 + nt) * 32 + lane];
#pragma unroll
                        for (int mi = 0; mi < 2; ++mi) { MMA3(acc[g][nt][mi], ah[mi], al[mi], b); }
                    }
                }
            }
#pragma unroll 2
            for (int ch = 8; ch < 16; ++ch) {          // K 128..255 (h1): R,Z,N
                uint32_t ah[2][4], al[2][4];
                load_afrag(shi, slo, ch * 4096, rb0, pA0, ah, al);
                const int gl[3] = {0, 1, 3};
#pragma unroll
                for (int gi = 0; gi < 3; ++gi) {
                    const int g = gl[gi];
#pragma unroll
                    for (int nt = 0; nt < 2; ++nt) {
                        uint4 b = g_Q1[((ch * 4 + g) * 16 + js0 + nt) * 32 + lane];
#pragma unroll
                        for (int mi = 0; mi < 2; ++mi) { MMA3(acc[g][nt][mi], ah[mi], al[mi], b); }
                    }
                }
            }
            // epilogue L1 (pass p)
#pragma unroll
            for (int nt = 0; nt < 2; ++nt) {
                const int jb = p * 64 + wn * 16 + nt * 8 + pc * 2;
                const int wq = nt * 4 + pc;
#pragma unroll
                for (int mi = 0; mi < 2; ++mi)
#pragma unroll
                    for (int half = 0; half < 2; ++half) {
                        const int r = wm * 32 + mi * 16 + gr + half * 8;
                        const int off = (8 + p * 4 + wn) * 4096 + r * 32 + ((wq ^ (r & 7)) << 2);
                        uint32_t phi = *(const uint32_t*)(shi + off);
                        uint32_t plo = *(const uint32_t*)(slo + off);
                        float hp[2] = { bf_lo(phi) + bf_lo(plo), bf_hi(phi) + bf_hi(plo) };
                        float h2[2];
#pragma unroll
                        for (int e = 0; e < 2; ++e) {
                            int j = jb + e;
                            int c = half * 2 + e;
                            float rr = sigf(acc[0][nt][mi][c] + sb[512 + j]);
                            float zz = sigf(acc[1][nt][mi][c] + sb[640 + j]);
                            float nn = tanhf(acc[2][nt][mi][c] + sb[768 + j] +
                                             rr * (acc[3][nt][mi][c] + sb[896 + j]));
                            h2[e] = (1.f - zz) * nn + zz * hp[e];
                        }
                        int hidx = (nt * 2 + mi) * 2 + half;
                        hHi[p][hidx] = pack_bf16x2(h2[0], h2[1], hLo[p][hidx]);
                    }
            }
        }
        __syncthreads();
        // write h1 (chunks 8..15)
#pragma unroll
        for (int p = 0; p < 2; ++p)
#pragma unroll
            for (int nt = 0; nt < 2; ++nt)
#pragma unroll
                for (int mi = 0; mi < 2; ++mi)
#pragma unroll
                    for (int half = 0; half < 2; ++half) {
                        const int r = wm * 32 + mi * 16 + gr + half * 8;
                        const int wq = nt * 4 + pc;
                        const int off = (8 + p * 4 + wn) * 4096 + r * 32 + ((wq ^ (r & 7)) << 2);
                        int hidx = (nt * 2 + mi) * 2 + half;
                        *(uint32_t*)(shi + off) = hHi[p][hidx];
                        *(uint32_t*)(slo + off) = hLo[p][hidx];
                    }
        __syncthreads();
    }

    // final: h1 smem -> g_h1 fp32
    for (int i = tid; i < 8192; i += 512) {
        int r = i >> 6, pr = i & 63;
        int j = pr * 2;
        int c = 8 + (j >> 4), wq = (j & 15) >> 1;
        int off = c * 4096 + r * 32 + ((wq ^ (r & 7)) << 2);
        uint32_t phi = *(const uint32_t*)(shi + off);
        uint32_t plo = *(const uint32_t*)(slo + off);
        float2 o = make_float2(bf_lo(phi) + bf_lo(plo), bf_hi(phi) + bf_hi(plo));
        *(float2*)(g_h1 + (size_t)(m0 + r) * TH + j) = o;
    }
}

// ---- node stage 1: LN(h1) -> xp, attention scores ----
__global__ void node_stage1(const float* __restrict__ ln_g, const float* __restrict__ ln_b,
                            const float* __restrict__ gatW,
                            const float* __restrict__ att_s, const float* __restrict__ att_d) {
    __shared__ float ts[8][TH];
    const int lane = threadIdx.x & 31, warp = threadIdx.x >> 5;
    const int m = blockIdx.x * 8 + warp;
    const float* hr = g_h1 + (size_t)m * TH;
    float v[4], s = 0.f, sq = 0.f;
#pragma unroll
    for (int i = 0; i < 4; ++i) { v[i] = hr[lane + 32 * i]; s += v[i]; sq += v[i] * v[i]; }
#pragma unroll
    for (int o = 16; o; o >>= 1) {
        s  += __shfl_xor_sync(0xffffffffu, s, o);
        sq += __shfl_xor_sync(0xffffffffu, sq, o);
    }
    float mu = s * (1.f / TH), var = sq * (1.f / TH) - mu * mu, inv = rsqrtf(var + 1e-5f);
#pragma unroll
    for (int i = 0; i < 4; ++i) {
        int k = lane + 32 * i;
        ts[warp][k] = (v[i] - mu) * inv * ln_g[k] + ln_b[k];
    }
    __syncwarp();
    float x0 = 0.f, x1 = 0.f;
#pragma unroll 4
    for (int k = 0; k < TH; ++k) {
        float tv = ts[warp][k];
        x0 = fmaf(tv, gatW[k * SH + lane], x0);
        x1 = fmaf(tv, gatW[k * SH + lane + 32], x1);
    }
    g_xp[(size_t)m * SH + lane] = x0;
    g_xp[(size_t)m * SH + lane + 32] = x1;
    float ps0 = x0 * att_s[lane], ps1 = x1 * att_s[lane + 32];
    float pd0 = x0 * att_d[lane], pd1 = x1 * att_d[lane + 32];
#pragma unroll
    for (int o = 8; o; o >>= 1) {
        ps0 += __shfl_xor_sync(0xffffffffu, ps0, o, 16);
        ps1 += __shfl_xor_sync(0xffffffffu, ps1, o, 16);
        pd0 += __shfl_xor_sync(0xffffffffu, pd0, o, 16);
        pd1 += __shfl_xor_sync(0xffffffffu, pd1, o, 16);
    }
    if ((lane & 15) == 0) {
        int h = lane >> 4;
        g_asrc[m * HEADS + h] = ps0;  g_asrc[m * HEADS + 2 + h] = ps1;
        g_adst[m * HEADS + h] = pd0;  g_adst[m * HEADS + 2 + h] = pd1;
    }
}

// ---- edge pass ----
__global__ void edge_kernel(const int* __restrict__ ei32) {
    int idx = blockIdx.x * blockDim.x + threadIdx.x;
    if (idx >= ET * HEADS) return;
    int h = idx & 3, e = idx >> 2, s, d;
    if (e < Bv * EB) {
        int g = e / EB, i = e - g * EB;
        if (g_ei_is64) { s = ei32[2 * i] + g * Nv; d = ei32[2 * (EB + i)] + g * Nv; }
        else           { s = ei32[i] + g * Nv;     d = ei32[EB + i] + g * Nv; }
    } else s = d = e - Bv * EB;
    float al = g_asrc[s * HEADS + h] + g_adst[d * HEADS + h];
    al = al > 0.f ? al : 0.2f * al;
    float ex = expf(al);
    atomicAdd(&g_den[d * HEADS + h], ex);
    const float* xr = g_xp + (size_t)s * SH + h * 16;
    float* ar = g_agg + (size_t)d * SH + h * 16;
#pragma unroll
    for (int c = 0; c < 16; ++c) atomicAdd(&ar[c], ex * xr[c]);
}

// ---- node stage 2 ----
__global__ void node_stage2(const float* __restrict__ gat_b,
                            const float* __restrict__ ln_g, const float* __restrict__ ln_b,
                            const float* __restrict__ W1, const float* __restrict__ b1,
                            const float* __restrict__ W2, const float* __restrict__ b2,
                            float* __restrict__ out) {
    __shared__ float ys[8][SH];
    const int lane = threadIdx.x & 31, warp = threadIdx.x >> 5;
    const int m = blockIdx.x * 8 + warp;
    float s0 = g_agg[(size_t)m * SH + lane]      / g_den[m * HEADS + (lane >> 4)]     + gat_b[lane];
    float s1 = g_agg[(size_t)m * SH + lane + 32] / g_den[m * HEADS + 2 + (lane >> 4)] + gat_b[lane + 32];
    float s = s0 + s1, sq = s0 * s0 + s1 * s1;
#pragma unroll
    for (int o = 16; o; o >>= 1) {
        s  += __shfl_xor_sync(0xffffffffu, s, o);
        sq += __shfl_xor_sync(0xffffffffu, sq, o);
    }
    float mu = s * (1.f / SH), var = sq * (1.f / SH) - mu * mu, inv = rsqrtf(var + 1e-5f);
    float y0 = (s0 - mu) * inv * ln_g[lane] + ln_b[lane];
    float y1 = (s1 - mu) * inv * ln_g[lane + 32] + ln_b[lane + 32];
    y0 = y0 > 0.f ? y0 : 0.2f * y0;
    y1 = y1 > 0.f ? y1 : 0.2f * y1;
    ys[warp][lane] = y0; ys[warp][lane + 32] = y1;
    __syncwarp();
    float acc = b1[lane];
#pragma unroll
    for (int k = 0; k < SH; ++k) acc = fmaf(ys[warp][k], W1[k * 32 + lane], acc);
    acc = acc > 0.f ? acc : 0.2f * acc;
    float p = acc * W2[lane];
#pragma unroll
    for (int o = 16; o; o >>= 1) p += __shfl_xor_sync(0xffffffffu, p, o);
    if (lane == 0) out[m] = p + b2[0];
}

extern "C" void kernel_launch(void* const* d_in, const int* in_sizes, int n_in,
                              void* d_out, int out_size) {
    const float* x     = (const float*)d_in[0];
    const int*   ei32  = (const int*)d_in[1];
    const float* W_ih0 = (const float*)d_in[2];
    const float* W_hh0 = (const float*)d_in[3];
    const float* b_ih0 = (const float*)d_in[4];
    const float* b_hh0 = (const float*)d_in[5];
    const float* W_ih1 = (const float*)d_in[6];
    const float* W_hh1 = (const float*)d_in[7];
    const float* b_ih1 = (const float*)d_in[8];
    const float* b_hh1 = (const float*)d_in[9];
    const float* ln1_g = (const float*)d_in[10];
    const float* ln1_b = (const float*)d_in[11];
    const float* gat_W = (const float*)d_in[12];
    const float* att_s = (const float*)d_in[13];
    const float* att_d = (const float*)d_in[14];
    const float* gat_b = (const float*)d_in[15];
    const float* ln2_g = (const float*)d_in[16];
    const float* ln2_b = (const float*)d_in[17];
    const float* regW1 = (const float*)d_in[18];
    const float* regb1 = (const float*)d_in[19];
    const float* regW2 = (const float*)d_in[20];
    const float* regb2 = (const float*)d_in[21];
    float* out = (float*)d_out;

    const int SMEM = 131072 + 7680 + 4096;   // 142848
    cudaFuncSetAttribute(gru_all, cudaFuncAttributeMaxDynamicSharedMemorySize, SMEM);

    detect_ei_kernel<<<1, 256>>>(ei32);
    prep_pack<<<(Q1N + Q0N + 255) / 256, 256>>>(W_ih1, W_hh1, W_hh0);
    zero_kernel<<<2048, 512>>>();

    gru_all<<<250, 512, SMEM>>>(x, W_ih0, b_ih0, b_hh0, b_ih1, b_hh1);

    node_stage1<<<Mn / 8, 256>>>(ln1_g, ln1_b, gat_W, att_s, att_d);
    edge_kernel<<<(ET * HEADS + 255) / 256, 256>>>(ei32);
    node_stage2<<<Mn / 8, 256>>>(gat_b, ln2_g, ln2_b, regW1, regb1, regW2, regb2, out);
}

// round 8
// speedup vs baseline: 3.9361x; 1.1777x over previous
#include <cuda_runtime.h>
#include <cuda_bf16.h>
#include <math.h>
#include <stdint.h>

constexpr int Bv = 16, Nv = 2000, Wv = 32, Fv = 5;
constexpr int TH = 128, SH = 64, HEADS = 4;
constexpr int Mn = Bv * Nv, EB = 32000, ET = Bv * EB + Mn;

// ---------------- device scratch ----------------
__device__ float g_h1[(size_t)Mn * TH];
__device__ float g_xp[(size_t)Mn * SH];
__device__ float g_asrc[Mn * HEADS];
__device__ float g_adst[Mn * HEADS];
__device__ float g_den[Mn * HEADS];
__device__ float g_agg[(size_t)Mn * SH];
__device__ int   g_ei_is64;
// B packs: uint4 = (bh_r0, bh_r1, bl_r0, bl_r1) per (ch, gate, jslot, lane)
constexpr int Q1N = 16 * 4 * 16 * 32;   // 32768
constexpr int Q0N = 8 * 3 * 16 * 32;    // 12288
__device__ uint4 g_Q1[Q1N];
__device__ uint4 g_Q0[Q0N];

__device__ __forceinline__ float sigf(float x) {
    return __fdividef(1.f, 1.f + __expf(-x));
}
__device__ __forceinline__ float tanhfast(float x) {
    float e = __expf(2.f * x);
    return 1.f - __fdividef(2.f, e + 1.f);
}

__device__ __forceinline__ void mma16816(float* c, const uint32_t* a,
                                         uint32_t b0, uint32_t b1) {
    asm volatile(
        "mma.sync.aligned.m16n8k16.row.col.f32.bf16.bf16.f32 "
        "{%0,%1,%2,%3}, {%4,%5,%6,%7}, {%8,%9}, {%0,%1,%2,%3};\n"
        : "+f"(c[0]), "+f"(c[1]), "+f"(c[2]), "+f"(c[3])
        : "r"(a[0]), "r"(a[1]), "r"(a[2]), "r"(a[3]), "r"(b0), "r"(b1));
}

__device__ __forceinline__ uint32_t pack_bf16x2(float f0, float f1, uint32_t& lo_out) {
    __nv_bfloat16 h0 = __float2bfloat16(f0);
    __nv_bfloat16 h1 = __float2bfloat16(f1);
    __nv_bfloat16 l0 = __float2bfloat16(f0 - __bfloat162float(h0));
    __nv_bfloat16 l1 = __float2bfloat16(f1 - __bfloat162float(h1));
    lo_out = (uint32_t)__bfloat16_as_ushort(l0) | ((uint32_t)__bfloat16_as_ushort(l1) << 16);
    return (uint32_t)__bfloat16_as_ushort(h0) | ((uint32_t)__bfloat16_as_ushort(h1) << 16);
}
__device__ __forceinline__ float bf_lo(uint32_t w) {
    return __bfloat162float(__ushort_as_bfloat16((unsigned short)(w & 0xffff)));
}
__device__ __forceinline__ float bf_hi(uint32_t w) {
    return __bfloat162float(__ushort_as_bfloat16((unsigned short)(w >> 16)));
}

// fragment-native state address: value pair (r, jp) (jp = k_in_chunk/2)
__device__ __forceinline__ int st_addr(int chunk, int r, int jp) {
    return chunk * 4096 + ((r >> 5) << 10) + (((r >> 4) & 1) << 9) +
           (((((r & 7) << 2) | (jp & 3))) << 4) +
           (((jp >> 2) << 1) | ((r >> 3) & 1)) * 4;
}

// ---------------- edge-index dtype probe ----------------
__global__ void detect_ei_kernel(const int* __restrict__ w) {
    __shared__ int nz;
    if (threadIdx.x == 0) nz = 0;
    __syncthreads();
    for (int i = threadIdx.x; i < 2048; i += blockDim.x)
        if ((i & 1) && w[i] != 0) atomicOr(&nz, 1);
    __syncthreads();
    if (threadIdx.x == 0) g_ei_is64 = nz ? 0 : 1;
}

// ---------------- prep: pack weights into uint4 MMA fragments ----------------
__global__ void prep_pack(const float* __restrict__ Wih1,
                          const float* __restrict__ Whh1,
                          const float* __restrict__ Whh0) {
    int idx = blockIdx.x * blockDim.x + threadIdx.x;
    if (idx < Q1N) {
        int lane = idx & 31, js = (idx >> 5) & 15, g = (idx >> 9) & 3, ch = idx >> 11;
        int j = js * 8 + (lane >> 2);
        float v[2][2];
#pragma unroll
        for (int r = 0; r < 2; ++r) {
            int k0 = ch * 16 + (lane & 3) * 2 + r * 8;
            float a = 0.f, b = 0.f;
            if (ch < 8) {
                if (g < 3) {
                    const float* Wr = Wih1 + (size_t)(g * 128 + j) * 128;
                    a = Wr[k0]; b = Wr[k0 + 1];
                }
            } else {
                int km = k0 - 128;
                if (g != 2) {
                    int gg = (g == 3) ? 2 : g;
                    const float* Wr = Whh1 + (size_t)(gg * 128 + j) * 128;
                    a = Wr[km]; b = Wr[km + 1];
                }
            }
            v[r][0] = a; v[r][1] = b;
        }
        uint4 o;
        uint32_t lo0, lo1;
        o.x = pack_bf16x2(v[0][0], v[0][1], lo0);
        o.y = pack_bf16x2(v[1][0], v[1][1], lo1);
        o.z = lo0; o.w = lo1;
        g_Q1[idx] = o;
    } else if (idx < Q1N + Q0N) {
        int i0 = idx - Q1N;
        int lane = i0 & 31, js = (i0 >> 5) & 15;
        int rest = i0 >> 9;
        int g = rest % 3, ch = rest / 3;
        int j = js * 8 + (lane >> 2);
        const float* Wr = Whh0 + (size_t)(g * 128 + j) * 128;
        uint4 o;
        uint32_t lo0, lo1;
        int k0 = ch * 16 + (lane & 3) * 2;
        o.x = pack_bf16x2(Wr[k0], Wr[k0 + 1], lo0);
        o.y = pack_bf16x2(Wr[k0 + 8], Wr[k0 + 9], lo1);
        o.z = lo0; o.w = lo1;
        g_Q0[i0] = o;
    }
}

__global__ void zero_kernel() {
    size_t stride = (size_t)gridDim.x * blockDim.x;
    for (size_t i = (size_t)blockIdx.x * blockDim.x + threadIdx.x;
         i < (size_t)Mn * SH; i += stride) {
        g_agg[i] = 0.f;
        if (i < (size_t)Mn * HEADS) g_den[i] = 0.f;
    }
}

#define MMA3(accp, ahv, alv, bq)              \
    mma16816(accp, ahv, (bq).x, (bq).y);      \
    mma16816(accp, alv, (bq).x, (bq).y);      \
    mma16816(accp, ahv, (bq).z, (bq).w);

// ===== persistent GRU: grid 250, block 512 (16 warps) =====
__global__ __launch_bounds__(512, 1)
void gru_all(const float* __restrict__ X, const float* __restrict__ Wih0,
             const float* __restrict__ bi0, const float* __restrict__ bh0,
             const float* __restrict__ bi1, const float* __restrict__ bh1) {
    extern __shared__ char sm[];
    char* shi = sm;                           // 16 chunks * 4KB (bf16 hi)
    char* slo = sm + 65536;                   // 64KB (bf16 lo)
    float* sW = (float*)(sm + 131072);        // Wih0: 1920 floats
    float* sb = (float*)(sm + 131072 + 7680); // biases: [L][4][128]

    const int tid = threadIdx.x, lane = tid & 31, wid = tid >> 5;
    const int wm = wid >> 2, wn = wid & 3, gr = lane >> 2, pc = lane & 3;
    const int m0 = blockIdx.x * 128;
    // per-warp fragment base (without chunk term)
    const int fragbase = wm * 1024 + lane * 16;

    {
        uint4 z = make_uint4(0, 0, 0, 0);
        for (int i = tid; i < 4096; i += 512) {
            ((uint4*)shi)[i] = z;
            ((uint4*)slo)[i] = z;
        }
    }
    for (int i = tid; i < 384 * Fv; i += 512) sW[i] = Wih0[i];
    for (int i = tid; i < 1024; i += 512) {
        int j = i & 127, which = (i >> 7) & 3, L = i >> 9;
        const float* BI = L ? bi1 : bi0;
        const float* BH = L ? bh1 : bh0;
        float v;
        if (which == 0)      v = BI[j] + BH[j];
        else if (which == 1) v = BI[128 + j] + BH[128 + j];
        else if (which == 2) v = BI[256 + j];
        else                 v = BH[256 + j];
        sb[i] = v;
    }
    __syncthreads();

    for (int t = 0; t < Wv; ++t) {
        uint4 hqh[2][2], hql[2][2];   // [pass][mi]

        // ================= LAYER 0 =================
        for (int p = 0; p < 2; ++p) {
            float acc[3][2][2][4];
#pragma unroll
            for (int g = 0; g < 3; ++g)
#pragma unroll
                for (int nt = 0; nt < 2; ++nt)
#pragma unroll
                    for (int mi = 0; mi < 2; ++mi)
#pragma unroll
                        for (int e = 0; e < 4; ++e) acc[g][nt][mi][e] = 0.f;
            const int js0 = p * 8 + wn * 2;
#pragma unroll 2
            for (int ch = 0; ch < 8; ++ch) {
                const int cb = ch * 4096 + fragbase;
                uint32_t ah[2][4], al[2][4];
#pragma unroll
                for (int mi = 0; mi < 2; ++mi) {
                    uint4 vh = *(const uint4*)(shi + cb + mi * 512);
                    uint4 vl = *(const uint4*)(slo + cb + mi * 512);
                    ah[mi][0] = vh.x; ah[mi][1] = vh.y; ah[mi][2] = vh.z; ah[mi][3] = vh.w;
                    al[mi][0] = vl.x; al[mi][1] = vl.y; al[mi][2] = vl.z; al[mi][3] = vl.w;
                }
#pragma unroll
                for (int g = 0; g < 3; ++g)
#pragma unroll
                    for (int nt = 0; nt < 2; ++nt) {
                        uint4 b = g_Q0[((ch * 3 + g) * 16 + js0 + nt) * 32 + lane];
#pragma unroll
                        for (int mi = 0; mi < 2; ++mi) { MMA3(acc[g][nt][mi], ah[mi], al[mi], b); }
                    }
            }
            // epilogue L0 (pass p): hp + gates, staged as uint4 per mi
#pragma unroll
            for (int mi = 0; mi < 2; ++mi) {
                const int hpaddr = (p * 4 + wn) * 4096 + fragbase + mi * 512;
                uint4 ph = *(const uint4*)(shi + hpaddr);
                uint4 pl = *(const uint4*)(slo + hpaddr);
                uint32_t phA[4] = {ph.x, ph.y, ph.z, ph.w};
                uint32_t plA[4] = {pl.x, pl.y, pl.z, pl.w};
                uint32_t vhi[4], vlo[4];
#pragma unroll
                for (int half = 0; half < 2; ++half) {
                    const int r = wm * 32 + mi * 16 + gr + half * 8;
                    const int m = m0 + r;
                    float xv[Fv];
                    const float* xr = X + ((size_t)m * Wv + t) * Fv;
#pragma unroll
                    for (int f = 0; f < Fv; ++f) xv[f] = xr[f];
#pragma unroll
                    for (int nt = 0; nt < 2; ++nt) {
                        const int fi = nt * 2 + half;
                        const int jb = p * 64 + wn * 16 + nt * 8 + pc * 2;
                        float hp[2] = { bf_lo(phA[fi]) + bf_lo(plA[fi]),
                                        bf_hi(phA[fi]) + bf_hi(plA[fi]) };
                        float h2[2];
#pragma unroll
                        for (int e = 0; e < 2; ++e) {
                            int j = jb + e;
                            float sR = 0.f, sZ = 0.f, sI = 0.f;
#pragma unroll
                            for (int f = 0; f < Fv; ++f) {
                                sR = fmaf(xv[f], sW[j * Fv + f], sR);
                                sZ = fmaf(xv[f], sW[(128 + j) * Fv + f], sZ);
                                sI = fmaf(xv[f], sW[(256 + j) * Fv + f], sI);
                            }
                            int c = half * 2 + e;
                            float rr = sigf(acc[0][nt][mi][c] + sR + sb[j]);
                            float zz = sigf(acc[1][nt][mi][c] + sZ + sb[128 + j]);
                            float nn = tanhfast(sI + sb[256 + j] +
                                                rr * (acc[2][nt][mi][c] + sb[384 + j]));
                            h2[e] = (1.f - zz) * nn + zz * hp[e];
                        }
                        vhi[fi] = pack_bf16x2(h2[0], h2[1], vlo[fi]);
                    }
                }
                hqh[p][mi] = make_uint4(vhi[0], vhi[1], vhi[2], vhi[3]);
                hql[p][mi] = make_uint4(vlo[0], vlo[1], vlo[2], vlo[3]);
            }
        }
        __syncthreads();
#pragma unroll
        for (int p = 0; p < 2; ++p)
#pragma unroll
            for (int mi = 0; mi < 2; ++mi) {
                const int a = (p * 4 + wn) * 4096 + fragbase + mi * 512;
                *(uint4*)(shi + a) = hqh[p][mi];
                *(uint4*)(slo + a) = hql[p][mi];
            }
        __syncthreads();

        // ================= LAYER 1 =================
        for (int p = 0; p < 2; ++p) {
            float acc[4][2][2][4];
#pragma unroll
            for (int g = 0; g < 4; ++g)
#pragma unroll
                for (int nt = 0; nt < 2; ++nt)
#pragma unroll
                    for (int mi = 0; mi < 2; ++mi)
#pragma unroll
                        for (int e = 0; e < 4; ++e) acc[g][nt][mi][e] = 0.f;
            const int js0 = p * 8 + wn * 2;
#pragma unroll 2
            for (int ch = 0; ch < 8; ++ch) {           // K 0..127 (h0): R,Z,I
                const int cb = ch * 4096 + fragbase;
                uint32_t ah[2][4], al[2][4];
#pragma unroll
                for (int mi = 0; mi < 2; ++mi) {
                    uint4 vh = *(const uint4*)(shi + cb + mi * 512);
                    uint4 vl = *(const uint4*)(slo + cb + mi * 512);
                    ah[mi][0] = vh.x; ah[mi][1] = vh.y; ah[mi][2] = vh.z; ah[mi][3] = vh.w;
                    al[mi][0] = vl.x; al[mi][1] = vl.y; al[mi][2] = vl.z; al[mi][3] = vl.w;
                }
                const int gl[3] = {0, 1, 2};
#pragma unroll
                for (int gi = 0; gi < 3; ++gi) {
                    const int g = gl[gi];
#pragma unroll
                    for (int nt = 0; nt < 2; ++nt) {
                        uint4 b = g_Q1[((ch * 4 + g) * 16 + js0 + nt) * 32 + lane];
#pragma unroll
                        for (int mi = 0; mi < 2; ++mi) { MMA3(acc[g][nt][mi], ah[mi], al[mi], b); }
                    }
                }
            }
#pragma unroll 2
            for (int ch = 8; ch < 16; ++ch) {          // K 128..255 (h1): R,Z,N
                const int cb = ch * 4096 + fragbase;
                uint32_t ah[2][4], al[2][4];
#pragma unroll
                for (int mi = 0; mi < 2; ++mi) {
                    uint4 vh = *(const uint4*)(shi + cb + mi * 512);
                    uint4 vl = *(const uint4*)(slo + cb + mi * 512);
                    ah[mi][0] = vh.x; ah[mi][1] = vh.y; ah[mi][2] = vh.z; ah[mi][3] = vh.w;
                    al[mi][0] = vl.x; al[mi][1] = vl.y; al[mi][2] = vl.z; al[mi][3] = vl.w;
                }
                const int gl[3] = {0, 1, 3};
#pragma unroll
                for (int gi = 0; gi < 3; ++gi) {
                    const int g = gl[gi];
#pragma unroll
                    for (int nt = 0; nt < 2; ++nt) {
                        uint4 b = g_Q1[((ch * 4 + g) * 16 + js0 + nt) * 32 + lane];
#pragma unroll
                        for (int mi = 0; mi < 2; ++mi) { MMA3(acc[g][nt][mi], ah[mi], al[mi], b); }
                    }
                }
            }
            // epilogue L1 (pass p)
#pragma unroll
            for (int mi = 0; mi < 2; ++mi) {
                const int hpaddr = (8 + p * 4 + wn) * 4096 + fragbase + mi * 512;
                uint4 ph = *(const uint4*)(shi + hpaddr);
                uint4 pl = *(const uint4*)(slo + hpaddr);
                uint32_t phA[4] = {ph.x, ph.y, ph.z, ph.w};
                uint32_t plA[4] = {pl.x, pl.y, pl.z, pl.w};
                uint32_t vhi[4], vlo[4];
#pragma unroll
                for (int half = 0; half < 2; ++half) {
#pragma unroll
                    for (int nt = 0; nt < 2; ++nt) {
                        const int fi = nt * 2 + half;
                        const int jb = p * 64 + wn * 16 + nt * 8 + pc * 2;
                        float hp[2] = { bf_lo(phA[fi]) + bf_lo(plA[fi]),
                                        bf_hi(phA[fi]) + bf_hi(plA[fi]) };
                        float h2[2];
#pragma unroll
                        for (int e = 0; e < 2; ++e) {
                            int j = jb + e;
                            int c = half * 2 + e;
                            float rr = sigf(acc[0][nt][mi][c] + sb[512 + j]);
                            float zz = sigf(acc[1][nt][mi][c] + sb[640 + j]);
                            float nn = tanhfast(acc[2][nt][mi][c] + sb[768 + j] +
                                                rr * (acc[3][nt][mi][c] + sb[896 + j]));
                            h2[e] = (1.f - zz) * nn + zz * hp[e];
                        }
                        vhi[fi] = pack_bf16x2(h2[0], h2[1], vlo[fi]);
                    }
                }
                hqh[p][mi] = make_uint4(vhi[0], vhi[1], vhi[2], vhi[3]);
                hql[p][mi] = make_uint4(vlo[0], vlo[1], vlo[2], vlo[3]);
            }
        }
        __syncthreads();
#pragma unroll
        for (int p = 0; p < 2; ++p)
#pragma unroll
            for (int mi = 0; mi < 2; ++mi) {
                const int a = (8 + p * 4 + wn) * 4096 + fragbase + mi * 512;
                *(uint4*)(shi + a) = hqh[p][mi];
                *(uint4*)(slo + a) = hql[p][mi];
            }
        __syncthreads();
    }

    // final: h1 smem -> g_h1 fp32
    for (int i = tid; i < 8192; i += 512) {
        int r = i >> 6, j = (i & 63) * 2;
        int chunk = 8 + (j >> 4), jp = (j >> 1) & 7;
        int off = st_addr(chunk, r, jp);
        uint32_t phi = *(const uint32_t*)(shi + off);
        uint32_t plo = *(const uint32_t*)(slo + off);
        float2 o = make_float2(bf_lo(phi) + bf_lo(plo), bf_hi(phi) + bf_hi(plo));
        *(float2*)(g_h1 + (size_t)(m0 + r) * TH + j) = o;
    }
}

// ---- node stage 1: LN(h1) -> xp, attention scores ----
__global__ void node_stage1(const float* __restrict__ ln_g, const float* __restrict__ ln_b,
                            const float* __restrict__ gatW,
                            const float* __restrict__ att_s, const float* __restrict__ att_d) {
    __shared__ float ts[8][TH];
    const int lane = threadIdx.x & 31, warp = threadIdx.x >> 5;
    const int m = blockIdx.x * 8 + warp;
    const float* hr = g_h1 + (size_t)m * TH;
    float v[4], s = 0.f, sq = 0.f;
#pragma unroll
    for (int i = 0; i < 4; ++i) { v[i] = hr[lane + 32 * i]; s += v[i]; sq += v[i] * v[i]; }
#pragma unroll
    for (int o = 16; o; o >>= 1) {
        s  += __shfl_xor_sync(0xffffffffu, s, o);
        sq += __shfl_xor_sync(0xffffffffu, sq, o);
    }
    float mu = s * (1.f / TH), var = sq * (1.f / TH) - mu * mu, inv = rsqrtf(var + 1e-5f);
#pragma unroll
    for (int i = 0; i < 4; ++i) {
        int k = lane + 32 * i;
        ts[warp][k] = (v[i] - mu) * inv * ln_g[k] + ln_b[k];
    }
    __syncwarp();
    float x0 = 0.f, x1 = 0.f;
#pragma unroll 4
    for (int k = 0; k < TH; ++k) {
        float tv = ts[warp][k];
        x0 = fmaf(tv, gatW[k * SH + lane], x0);
        x1 = fmaf(tv, gatW[k * SH + lane + 32], x1);
    }
    g_xp[(size_t)m * SH + lane] = x0;
    g_xp[(size_t)m * SH + lane + 32] = x1;
    float ps0 = x0 * att_s[lane], ps1 = x1 * att_s[lane + 32];
    float pd0 = x0 * att_d[lane], pd1 = x1 * att_d[lane + 32];
#pragma unroll
    for (int o = 8; o; o >>= 1) {
        ps0 += __shfl_xor_sync(0xffffffffu, ps0, o, 16);
        ps1 += __shfl_xor_sync(0xffffffffu, ps1, o, 16);
        pd0 += __shfl_xor_sync(0xffffffffu, pd0, o, 16);
        pd1 += __shfl_xor_sync(0xffffffffu, pd1, o, 16);
    }
    if ((lane & 15) == 0) {
        int h = lane >> 4;
        g_asrc[m * HEADS + h] = ps0;  g_asrc[m * HEADS + 2 + h] = ps1;
        g_adst[m * HEADS + h] = pd0;  g_adst[m * HEADS + 2 + h] = pd1;
    }
}

// ---- edge pass ----
__global__ void edge_kernel(const int* __restrict__ ei32) {
    int idx = blockIdx.x * blockDim.x + threadIdx.x;
    if (idx >= ET * HEADS) return;
    int h = idx & 3, e = idx >> 2, s, d;
    if (e < Bv * EB) {
        int g = e / EB, i = e - g * EB;
        if (g_ei_is64) { s = ei32[2 * i] + g * Nv; d = ei32[2 * (EB + i)] + g * Nv; }
        else           { s = ei32[i] + g * Nv;     d = ei32[EB + i] + g * Nv; }
    } else s = d = e - Bv * EB;
    float al = g_asrc[s * HEADS + h] + g_adst[d * HEADS + h];
    al = al > 0.f ? al : 0.2f * al;
    float ex = __expf(al);
    atomicAdd(&g_den[d * HEADS + h], ex);
    const float* xr = g_xp + (size_t)s * SH + h * 16;
    float* ar = g_agg + (size_t)d * SH + h * 16;
#pragma unroll
    for (int c = 0; c < 16; ++c) atomicAdd(&ar[c], ex * xr[c]);
}

// ---- node stage 2 ----
__global__ void node_stage2(const float* __restrict__ gat_b,
                            const float* __restrict__ ln_g, const float* __restrict__ ln_b,
                            const float* __restrict__ W1, const float* __restrict__ b1,
                            const float* __restrict__ W2, const float* __restrict__ b2,
                            float* __restrict__ out) {
    __shared__ float ys[8][SH];
    const int lane = threadIdx.x & 31, warp = threadIdx.x >> 5;
    const int m = blockIdx.x * 8 + warp;
    float s0 = g_agg[(size_t)m * SH + lane]      / g_den[m * HEADS + (lane >> 4)]     + gat_b[lane];
    float s1 = g_agg[(size_t)m * SH + lane + 32] / g_den[m * HEADS + 2 + (lane >> 4)] + gat_b[lane + 32];
    float s = s0 + s1, sq = s0 * s0 + s1 * s1;
#pragma unroll
    for (int o = 16; o; o >>= 1) {
        s  += __shfl_xor_sync(0xffffffffu, s, o);
        sq += __shfl_xor_sync(0xffffffffu, sq, o);
    }
    float mu = s * (1.f / SH), var = sq * (1.f / SH) - mu * mu, inv = rsqrtf(var + 1e-5f);
    float y0 = (s0 - mu) * inv * ln_g[lane] + ln_b[lane];
    float y1 = (s1 - mu) * inv * ln_g[lane + 32] + ln_b[lane + 32];
    y0 = y0 > 0.f ? y0 : 0.2f * y0;
    y1 = y1 > 0.f ? y1 : 0.2f * y1;
    ys[warp][lane] = y0; ys[warp][lane + 32] = y1;
    __syncwarp();
    float acc = b1[lane];
#pragma unroll
    for (int k = 0; k < SH; ++k) acc = fmaf(ys[warp][k], W1[k * 32 + lane], acc);
    acc = acc > 0.f ? acc : 0.2f * acc;
    float p = acc * W2[lane];
#pragma unroll
    for (int o = 16; o; o >>= 1) p += __shfl_xor_sync(0xffffffffu, p, o);
    if (lane == 0) out[m] = p + b2[0];
}

extern "C" void kernel_launch(void* const* d_in, const int* in_sizes, int n_in,
                              void* d_out, int out_size) {
    const float* x     = (const float*)d_in[0];
    const int*   ei32  = (const int*)d_in[1];
    const float* W_ih0 = (const float*)d_in[2];
    const float* W_hh0 = (const float*)d_in[3];
    const float* b_ih0 = (const float*)d_in[4];
    const float* b_hh0 = (const float*)d_in[5];
    const float* W_ih1 = (const float*)d_in[6];
    const float* W_hh1 = (const float*)d_in[7];
    const float* b_ih1 = (const float*)d_in[8];
    const float* b_hh1 = (const float*)d_in[9];
    const float* ln1_g = (const float*)d_in[10];
    const float* ln1_b = (const float*)d_in[11];
    const float* gat_W = (const float*)d_in[12];
    const float* att_s = (const float*)d_in[13];
    const float* att_d = (const float*)d_in[14];
    const float* gat_b = (const float*)d_in[15];
    const float* ln2_g = (const float*)d_in[16];
    const float* ln2_b = (const float*)d_in[17];
    const float* regW1 = (const float*)d_in[18];
    const float* regb1 = (const float*)d_in[19];
    const float* regW2 = (const float*)d_in[20];
    const float* regb2 = (const float*)d_in[21];
    float* out = (float*)d_out;

    const int SMEM = 131072 + 7680 + 4096;   // 142848
    cudaFuncSetAttribute(gru_all, cudaFuncAttributeMaxDynamicSharedMemorySize, SMEM);

    detect_ei_kernel<<<1, 256>>>(ei32);
    prep_pack<<<(Q1N + Q0N + 255) / 256, 256>>>(W_ih1, W_hh1, W_hh0);
    zero_kernel<<<2048, 512>>>();

    gru_all<<<250, 512, SMEM>>>(x, W_ih0, b_ih0, b_hh0, b_ih1, b_hh1);

    node_stage1<<<Mn / 8, 256>>>(ln1_g, ln1_b, gat_W, att_s, att_d);
    edge_kernel<<<(ET * HEADS + 255) / 256, 256>>>(ei32);
    node_stage2<<<Mn / 8, 256>>>(gat_b, ln2_g, ln2_b, regW1, regb1, regW2, regb2, out);
}

// round 9
// speedup vs baseline: 4.0591x; 1.0313x over previous
#include <cuda_runtime.h>
#include <cuda_bf16.h>
#include <math.h>
#include <stdint.h>

constexpr int Bv = 16, Nv = 2000, Wv = 32, Fv = 5;
constexpr int TH = 128, SH = 64, HEADS = 4;
constexpr int Mn = Bv * Nv, EB = 32000, ET = Bv * EB + Mn;

// ---------------- device scratch ----------------
__device__ float g_h1[(size_t)Mn * TH];
__device__ float g_xp[(size_t)Mn * SH];
__device__ float g_asrc[Mn * HEADS];
__device__ float g_adst[Mn * HEADS];
__device__ float g_den[Mn * HEADS];
__device__ float g_agg[(size_t)Mn * SH];
__device__ int   g_ei_is64;
// B packs: uint4 = (bh_r0, bh_r1, bl_r0, bl_r1) per (ch, gate, jslot, lane)
constexpr int Q1N = 16 * 4 * 16 * 32;   // 32768
constexpr int Q0N = 8 * 3 * 16 * 32;    // 12288
__device__ uint4 g_Q1[Q1N];
__device__ uint4 g_Q0[Q0N];

__device__ __forceinline__ float sigf(float x) {
    return __fdividef(1.f, 1.f + __expf(-x));
}
__device__ __forceinline__ float tanhfast(float x) {
    float e = __expf(2.f * x);
    return 1.f - __fdividef(2.f, e + 1.f);
}

__device__ __forceinline__ void mma16816(float* c, const uint32_t* a,
                                         uint32_t b0, uint32_t b1) {
    asm volatile(
        "mma.sync.aligned.m16n8k16.row.col.f32.bf16.bf16.f32 "
        "{%0,%1,%2,%3}, {%4,%5,%6,%7}, {%8,%9}, {%0,%1,%2,%3};\n"
        : "+f"(c[0]), "+f"(c[1]), "+f"(c[2]), "+f"(c[3])
        : "r"(a[0]), "r"(a[1]), "r"(a[2]), "r"(a[3]), "r"(b0), "r"(b1));
}

__device__ __forceinline__ uint32_t pack_bf16x2(float f0, float f1, uint32_t& lo_out) {
    __nv_bfloat16 h0 = __float2bfloat16(f0);
    __nv_bfloat16 h1 = __float2bfloat16(f1);
    __nv_bfloat16 l0 = __float2bfloat16(f0 - __bfloat162float(h0));
    __nv_bfloat16 l1 = __float2bfloat16(f1 - __bfloat162float(h1));
    lo_out = (uint32_t)__bfloat16_as_ushort(l0) | ((uint32_t)__bfloat16_as_ushort(l1) << 16);
    return (uint32_t)__bfloat16_as_ushort(h0) | ((uint32_t)__bfloat16_as_ushort(h1) << 16);
}
__device__ __forceinline__ float bf_lo(uint32_t w) {
    return __bfloat162float(__ushort_as_bfloat16((unsigned short)(w & 0xffff)));
}
__device__ __forceinline__ float bf_hi(uint32_t w) {
    return __bfloat162float(__ushort_as_bfloat16((unsigned short)(w >> 16)));
}

// ---------------- edge-index dtype probe ----------------
__global__ void detect_ei_kernel(const int* __restrict__ w) {
    __shared__ int nz;
    if (threadIdx.x == 0) nz = 0;
    __syncthreads();
    for (int i = threadIdx.x; i < 2048; i += blockDim.x)
        if ((i & 1) && w[i] != 0) atomicOr(&nz, 1);
    __syncthreads();
    if (threadIdx.x == 0) g_ei_is64 = nz ? 0 : 1;
}

// ---------------- prep: pack weights into uint4 MMA fragments ----------------
__global__ void prep_pack(const float* __restrict__ Wih1,
                          const float* __restrict__ Whh1,
                          const float* __restrict__ Whh0) {
    int idx = blockIdx.x * blockDim.x + threadIdx.x;
    if (idx < Q1N) {
        int lane = idx & 31, js = (idx >> 5) & 15, g = (idx >> 9) & 3, ch = idx >> 11;
        int j = js * 8 + (lane >> 2);
        float v[2][2];
#pragma unroll
        for (int r = 0; r < 2; ++r) {
            int k0 = ch * 16 + (lane & 3) * 2 + r * 8;
            float a = 0.f, b = 0.f;
            if (ch < 8) {
                if (g < 3) {
                    const float* Wr = Wih1 + (size_t)(g * 128 + j) * 128;
                    a = Wr[k0]; b = Wr[k0 + 1];
                }
            } else {
                int km = k0 - 128;
                if (g != 2) {
                    int gg = (g == 3) ? 2 : g;
                    const float* Wr = Whh1 + (size_t)(gg * 128 + j) * 128;
                    a = Wr[km]; b = Wr[km + 1];
                }
            }
            v[r][0] = a; v[r][1] = b;
        }
        uint4 o;
        uint32_t lo0, lo1;
        o.x = pack_bf16x2(v[0][0], v[0][1], lo0);
        o.y = pack_bf16x2(v[1][0], v[1][1], lo1);
        o.z = lo0; o.w = lo1;
        g_Q1[idx] = o;
    } else if (idx < Q1N + Q0N) {
        int i0 = idx - Q1N;
        int lane = i0 & 31, js = (i0 >> 5) & 15;
        int rest = i0 >> 9;
        int g = rest % 3, ch = rest / 3;
        int j = js * 8 + (lane >> 2);
        const float* Wr = Whh0 + (size_t)(g * 128 + j) * 128;
        uint4 o;
        uint32_t lo0, lo1;
        int k0 = ch * 16 + (lane & 3) * 2;
        o.x = pack_bf16x2(Wr[k0], Wr[k0 + 1], lo0);
        o.y = pack_bf16x2(Wr[k0 + 8], Wr[k0 + 9], lo1);
        o.z = lo0; o.w = lo1;
        g_Q0[i0] = o;
    }
}

__global__ void zero_kernel() {
    size_t stride = (size_t)gridDim.x * blockDim.x;
    for (size_t i = (size_t)blockIdx.x * blockDim.x + threadIdx.x;
         i < (size_t)Mn * SH; i += stride) {
        g_agg[i] = 0.f;
        if (i < (size_t)Mn * HEADS) g_den[i] = 0.f;
    }
}

#define MMA3(accp, ahv, alv, bq)              \
    mma16816(accp, ahv, (bq).x, (bq).y);      \
    mma16816(accp, alv, (bq).x, (bq).y);      \
    mma16816(accp, ahv, (bq).z, (bq).w);

// ===== persistent GRU: grid 500 (M=64 tiles), block 256 (8 warps), 2 CTAs/SM =====
// smem layout: shi[16*2048] | slo[16*2048] | sW[1920 f] | sb[1024 f] | sX[320 f]
constexpr int SM_SLO = 32768;
constexpr int SM_SW  = 65536;
constexpr int SM_SB  = SM_SW + 7680;
constexpr int SM_SX  = SM_SB + 4096;
constexpr int SM_TOT = SM_SX + 1280;     // 78592

__global__ __launch_bounds__(256, 2)
void gru_all(const float* __restrict__ X, const float* __restrict__ Wih0,
             const float* __restrict__ bi0, const float* __restrict__ bh0,
             const float* __restrict__ bi1, const float* __restrict__ bh1) {
    extern __shared__ char sm[];
    char* shi = sm;
    char* slo = sm + SM_SLO;
    float* sW = (float*)(sm + SM_SW);
    float* sb = (float*)(sm + SM_SB);
    float* sX = (float*)(sm + SM_SX);

    const int tid = threadIdx.x, lane = tid & 31, wid = tid >> 5;
    const int wm = wid >> 2, wn = wid & 3;   // wm in {0,1}
    const int m0 = blockIdx.x * 64;
    const int fragbase = wm * 1024 + lane * 16;

    {
        uint4 z = make_uint4(0, 0, 0, 0);
        for (int i = tid; i < 2048; i += 256) {
            ((uint4*)shi)[i] = z;
            ((uint4*)slo)[i] = z;
        }
    }
    for (int i = tid; i < 384 * Fv; i += 256) sW[i] = Wih0[i];
    for (int i = tid; i < 1024; i += 256) {
        int j = i & 127, which = (i >> 7) & 3, L = i >> 9;
        const float* BI = L ? bi1 : bi0;
        const float* BH = L ? bh1 : bh0;
        float v;
        if (which == 0)      v = BI[j] + BH[j];
        else if (which == 1) v = BI[128 + j] + BH[128 + j];
        else if (which == 2) v = BI[256 + j];
        else                 v = BH[256 + j];
        sb[i] = v;
    }
    __syncthreads();

    for (int t = 0; t < Wv; ++t) {
        uint4 hqh[2][2], hql[2][2];   // [pass][mi]

        // X prefetch for this warp's rows (4 wn-warps write same data - benign)
        for (int i = lane; i < 160; i += 32) {
            int rr = i / 5, f = i - rr * 5;
            sX[wm * 160 + i] = X[((size_t)(m0 + wm * 32 + rr) * Wv + t) * Fv + f];
        }

        // ================= LAYER 0 =================
        for (int p = 0; p < 2; ++p) {
            float acc[3][2][2][4];
#pragma unroll
            for (int g = 0; g < 3; ++g)
#pragma unroll
                for (int nt = 0; nt < 2; ++nt)
#pragma unroll
                    for (int mi = 0; mi < 2; ++mi)
#pragma unroll
                        for (int e = 0; e < 4; ++e) acc[g][nt][mi][e] = 0.f;
            const int js0 = p * 8 + wn * 2;
#pragma unroll 2
            for (int ch = 0; ch < 8; ++ch) {
                const int cb = ch * 2048 + fragbase;
                uint32_t ah[2][4], al[2][4];
#pragma unroll
                for (int mi = 0; mi < 2; ++mi) {
                    uint4 vh = *(const uint4*)(shi + cb + mi * 512);
                    uint4 vl = *(const uint4*)(slo + cb + mi * 512);
                    ah[mi][0] = vh.x; ah[mi][1] = vh.y; ah[mi][2] = vh.z; ah[mi][3] = vh.w;
                    al[mi][0] = vl.x; al[mi][1] = vl.y; al[mi][2] = vl.z; al[mi][3] = vl.w;
                }
#pragma unroll
                for (int g = 0; g < 3; ++g)
#pragma unroll
                    for (int nt = 0; nt < 2; ++nt) {
                        uint4 b = g_Q0[((ch * 3 + g) * 16 + js0 + nt) * 32 + lane];
#pragma unroll
                        for (int mi = 0; mi < 2; ++mi) { MMA3(acc[g][nt][mi], ah[mi], al[mi], b); }
                    }
            }
            __syncwarp();
            // epilogue L0 (pass p)
#pragma unroll
            for (int mi = 0; mi < 2; ++mi) {
                const int hpaddr = (p * 4 + wn) * 2048 + fragbase + mi * 512;
                uint4 ph = *(const uint4*)(shi + hpaddr);
                uint4 pl = *(const uint4*)(slo + hpaddr);
                uint32_t phA[4] = {ph.x, ph.y, ph.z, ph.w};
                uint32_t plA[4] = {pl.x, pl.y, pl.z, pl.w};
                uint32_t vhi[4], vlo[4];
#pragma unroll
                for (int half = 0; half < 2; ++half) {
                    const int r = wm * 32 + mi * 16 + (lane >> 2) + half * 8;
                    float xv[Fv];
#pragma unroll
                    for (int f = 0; f < Fv; ++f) xv[f] = sX[r * 5 + f];
#pragma unroll
                    for (int nt = 0; nt < 2; ++nt) {
                        const int fi = nt * 2 + half;
                        const int jb = p * 64 + wn * 16 + nt * 8 + (lane & 3) * 2;
                        float hp[2] = { bf_lo(phA[fi]) + bf_lo(plA[fi]),
                                        bf_hi(phA[fi]) + bf_hi(plA[fi]) };
                        float h2[2];
#pragma unroll
                        for (int e = 0; e < 2; ++e) {
                            int j = jb + e;
                            float sR = 0.f, sZ = 0.f, sI = 0.f;
#pragma unroll
                            for (int f = 0; f < Fv; ++f) {
                                sR = fmaf(xv[f], sW[j * Fv + f], sR);
                                sZ = fmaf(xv[f], sW[(128 + j) * Fv + f], sZ);
                                sI = fmaf(xv[f], sW[(256 + j) * Fv + f], sI);
                            }
                            int c = half * 2 + e;
                            float rr = sigf(acc[0][nt][mi][c] + sR + sb[j]);
                            float zz = sigf(acc[1][nt][mi][c] + sZ + sb[128 + j]);
                            float nn = tanhfast(sI + sb[256 + j] +
                                                rr * (acc[2][nt][mi][c] + sb[384 + j]));
                            h2[e] = (1.f - zz) * nn + zz * hp[e];
                        }
                        vhi[fi] = pack_bf16x2(h2[0], h2[1], vlo[fi]);
                    }
                }
                hqh[p][mi] = make_uint4(vhi[0], vhi[1], vhi[2], vhi[3]);
                hql[p][mi] = make_uint4(vlo[0], vlo[1], vlo[2], vlo[3]);
            }
        }
        __syncthreads();
#pragma unroll
        for (int p = 0; p < 2; ++p)
#pragma unroll
            for (int mi = 0; mi < 2; ++mi) {
                const int a = (p * 4 + wn) * 2048 + fragbase + mi * 512;
                *(uint4*)(shi + a) = hqh[p][mi];
                *(uint4*)(slo + a) = hql[p][mi];
            }
        __syncthreads();

        // ================= LAYER 1 =================
        for (int p = 0; p < 2; ++p) {
            float acc[4][2][2][4];
#pragma unroll
            for (int g = 0; g < 4; ++g)
#pragma unroll
                for (int nt = 0; nt < 2; ++nt)
#pragma unroll
                    for (int mi = 0; mi < 2; ++mi)
#pragma unroll
                        for (int e = 0; e < 4; ++e) acc[g][nt][mi][e] = 0.f;
            const int js0 = p * 8 + wn * 2;
#pragma unroll 2
            for (int ch = 0; ch < 8; ++ch) {           // K 0..127 (h0): R,Z,I
                const int cb = ch * 2048 + fragbase;
                uint32_t ah[2][4], al[2][4];
#pragma unroll
                for (int mi = 0; mi < 2; ++mi) {
                    uint4 vh = *(const uint4*)(shi + cb + mi * 512);
                    uint4 vl = *(const uint4*)(slo + cb + mi * 512);
                    ah[mi][0] = vh.x; ah[mi][1] = vh.y; ah[mi][2] = vh.z; ah[mi][3] = vh.w;
                    al[mi][0] = vl.x; al[mi][1] = vl.y; al[mi][2] = vl.z; al[mi][3] = vl.w;
                }
                const int gl[3] = {0, 1, 2};
#pragma unroll
                for (int gi = 0; gi < 3; ++gi) {
                    const int g = gl[gi];
#pragma unroll
                    for (int nt = 0; nt < 2; ++nt) {
                        uint4 b = g_Q1[((ch * 4 + g) * 16 + js0 + nt) * 32 + lane];
#pragma unroll
                        for (int mi = 0; mi < 2; ++mi) { MMA3(acc[g][nt][mi], ah[mi], al[mi], b); }
                    }
                }
            }
#pragma unroll 2
            for (int ch = 8; ch < 16; ++ch) {          // K 128..255 (h1): R,Z,N
                const int cb = ch * 2048 + fragbase;
                uint32_t ah[2][4], al[2][4];
#pragma unroll
                for (int mi = 0; mi < 2; ++mi) {
                    uint4 vh = *(const uint4*)(shi + cb + mi * 512);
                    uint4 vl = *(const uint4*)(slo + cb + mi * 512);
                    ah[mi][0] = vh.x; ah[mi][1] = vh.y; ah[mi][2] = vh.z; ah[mi][3] = vh.w;
                    al[mi][0] = vl.x; al[mi][1] = vl.y; al[mi][2] = vl.z; al[mi][3] = vl.w;
                }
                const int gl[3] = {0, 1, 3};
#pragma unroll
                for (int gi = 0; gi < 3; ++gi) {
                    const int g = gl[gi];
#pragma unroll
                    for (int nt = 0; nt < 2; ++nt) {
                        uint4 b = g_Q1[((ch * 4 + g) * 16 + js0 + nt) * 32 + lane];
#pragma unroll
                        for (int mi = 0; mi < 2; ++mi) { MMA3(acc[g][nt][mi], ah[mi], al[mi], b); }
                    }
                }
            }
            // epilogue L1 (pass p)
#pragma unroll
            for (int mi = 0; mi < 2; ++mi) {
                const int hpaddr = (8 + p * 4 + wn) * 2048 + fragbase + mi * 512;
                uint4 ph = *(const uint4*)(shi + hpaddr);
                uint4 pl = *(const uint4*)(slo + hpaddr);
                uint32_t phA[4] = {ph.x, ph.y, ph.z, ph.w};
                uint32_t plA[4] = {pl.x, pl.y, pl.z, pl.w};
                uint32_t vhi[4], vlo[4];
#pragma unroll
                for (int half = 0; half < 2; ++half) {
#pragma unroll
                    for (int nt = 0; nt < 2; ++nt) {
                        const int fi = nt * 2 + half;
                        const int jb = p * 64 + wn * 16 + nt * 8 + (lane & 3) * 2;
                        float hp[2] = { bf_lo(phA[fi]) + bf_lo(plA[fi]),
                                        bf_hi(phA[fi]) + bf_hi(plA[fi]) };
                        float h2[2];
#pragma unroll
                        for (int e = 0; e < 2; ++e) {
                            int j = jb + e;
                            int c = half * 2 + e;
                            float rr = sigf(acc[0][nt][mi][c] + sb[512 + j]);
                            float zz = sigf(acc[1][nt][mi][c] + sb[640 + j]);
                            float nn = tanhfast(acc[2][nt][mi][c] + sb[768 + j] +
                                                rr * (acc[3][nt][mi][c] + sb[896 + j]));
                            h2[e] = (1.f - zz) * nn + zz * hp[e];
                        }
                        vhi[fi] = pack_bf16x2(h2[0], h2[1], vlo[fi]);
                    }
                }
                hqh[p][mi] = make_uint4(vhi[0], vhi[1], vhi[2], vhi[3]);
                hql[p][mi] = make_uint4(vlo[0], vlo[1], vlo[2], vlo[3]);
            }
        }
        __syncthreads();
#pragma unroll
        for (int p = 0; p < 2; ++p)
#pragma unroll
            for (int mi = 0; mi < 2; ++mi) {
                const int a = (8 + p * 4 + wn) * 2048 + fragbase + mi * 512;
                *(uint4*)(shi + a) = hqh[p][mi];
                *(uint4*)(slo + a) = hql[p][mi];
            }
        __syncthreads();
    }

    // final: h1 smem -> g_h1 fp32 (64 rows x 64 col-pairs)
    for (int i = tid; i < 4096; i += 256) {
        int r = i >> 6, j = (i & 63) * 2;
        int chunk = 8 + (j >> 4), jp = (j >> 1) & 7;
        int off = chunk * 2048 + ((r >> 5) << 10) + (((r >> 4) & 1) << 9) +
                  ((((r & 7) << 2) | (jp & 3)) << 4) +
                  ((((jp >> 2) << 1) | ((r >> 3) & 1)) << 2);
        uint32_t phi = *(const uint32_t*)(shi + off);
        uint32_t plo = *(const uint32_t*)(slo + off);
        float2 o = make_float2(bf_lo(phi) + bf_lo(plo), bf_hi(phi) + bf_hi(plo));
        *(float2*)(g_h1 + (size_t)(m0 + r) * TH + j) = o;
    }
}

// ---- node stage 1: LN(h1) -> xp, attention scores ----
__global__ void node_stage1(const float* __restrict__ ln_g, const float* __restrict__ ln_b,
                            const float* __restrict__ gatW,
                            const float* __restrict__ att_s, const float* __restrict__ att_d) {
    __shared__ float ts[8][TH];
    const int lane = threadIdx.x & 31, warp = threadIdx.x >> 5;
    const int m = blockIdx.x * 8 + warp;
    const float* hr = g_h1 + (size_t)m * TH;
    float v[4], s = 0.f, sq = 0.f;
#pragma unroll
    for (int i = 0; i < 4; ++i) { v[i] = hr[lane + 32 * i]; s += v[i]; sq += v[i] * v[i]; }
#pragma unroll
    for (int o = 16; o; o >>= 1) {
        s  += __shfl_xor_sync(0xffffffffu, s, o);
        sq += __shfl_xor_sync(0xffffffffu, sq, o);
    }
    float mu = s * (1.f / TH), var = sq * (1.f / TH) - mu * mu, inv = rsqrtf(var + 1e-5f);
#pragma unroll
    for (int i = 0; i < 4; ++i) {
        int k = lane + 32 * i;
        ts[warp][k] = (v[i] - mu) * inv * ln_g[k] + ln_b[k];
    }
    __syncwarp();
    float x0 = 0.f, x1 = 0.f;
#pragma unroll 4
    for (int k = 0; k < TH; ++k) {
        float tv = ts[warp][k];
        x0 = fmaf(tv, gatW[k * SH + lane], x0);
        x1 = fmaf(tv, gatW[k * SH + lane + 32], x1);
    }
    g_xp[(size_t)m * SH + lane] = x0;
    g_xp[(size_t)m * SH + lane + 32] = x1;
    float ps0 = x0 * att_s[lane], ps1 = x1 * att_s[lane + 32];
    float pd0 = x0 * att_d[lane], pd1 = x1 * att_d[lane + 32];
#pragma unroll
    for (int o = 8; o; o >>= 1) {
        ps0 += __shfl_xor_sync(0xffffffffu, ps0, o, 16);
        ps1 += __shfl_xor_sync(0xffffffffu, ps1, o, 16);
        pd0 += __shfl_xor_sync(0xffffffffu, pd0, o, 16);
        pd1 += __shfl_xor_sync(0xffffffffu, pd1, o, 16);
    }
    if ((lane & 15) == 0) {
        int h = lane >> 4;
        g_asrc[m * HEADS + h] = ps0;  g_asrc[m * HEADS + 2 + h] = ps1;
        g_adst[m * HEADS + h] = pd0;  g_adst[m * HEADS + 2 + h] = pd1;
    }
}

// ---- edge pass ----
__global__ void edge_kernel(const int* __restrict__ ei32) {
    int idx = blockIdx.x * blockDim.x + threadIdx.x;
    if (idx >= ET * HEADS) return;
    int h = idx & 3, e = idx >> 2, s, d;
    if (e < Bv * EB) {
        int g = e / EB, i = e - g * EB;
        if (g_ei_is64) { s = ei32[2 * i] + g * Nv; d = ei32[2 * (EB + i)] + g * Nv; }
        else           { s = ei32[i] + g * Nv;     d = ei32[EB + i] + g * Nv; }
    } else s = d = e - Bv * EB;
    float al = g_asrc[s * HEADS + h] + g_adst[d * HEADS + h];
    al = al > 0.f ? al : 0.2f * al;
    float ex = __expf(al);
    atomicAdd(&g_den[d * HEADS + h], ex);
    const float* xr = g_xp + (size_t)s * SH + h * 16;
    float* ar = g_agg + (size_t)d * SH + h * 16;
#pragma unroll
    for (int c = 0; c < 16; ++c) atomicAdd(&ar[c], ex * xr[c]);
}

// ---- node stage 2 ----
__global__ void node_stage2(const float* __restrict__ gat_b,
                            const float* __restrict__ ln_g, const float* __restrict__ ln_b,
                            const float* __restrict__ W1, const float* __restrict__ b1,
                            const float* __restrict__ W2, const float* __restrict__ b2,
                            float* __restrict__ out) {
    __shared__ float ys[8][SH];
    const int lane = threadIdx.x & 31, warp = threadIdx.x >> 5;
    const int m = blockIdx.x * 8 + warp;
    float s0 = g_agg[(size_t)m * SH + lane]      / g_den[m * HEADS + (lane >> 4)]     + gat_b[lane];
    float s1 = g_agg[(size_t)m * SH + lane + 32] / g_den[m * HEADS + 2 + (lane >> 4)] + gat_b[lane + 32];
    float s = s0 + s1, sq = s0 * s0 + s1 * s1;
#pragma unroll
    for (int o = 16; o; o >>= 1) {
        s  += __shfl_xor_sync(0xffffffffu, s, o);
        sq += __shfl_xor_sync(0xffffffffu, sq, o);
    }
    float mu = s * (1.f / SH), var = sq * (1.f / SH) - mu * mu, inv = rsqrtf(var + 1e-5f);
    float y0 = (s0 - mu) * inv * ln_g[lane] + ln_b[lane];
    float y1 = (s1 - mu) * inv * ln_g[lane + 32] + ln_b[lane + 32];
    y0 = y0 > 0.f ? y0 : 0.2f * y0;
    y1 = y1 > 0.f ? y1 : 0.2f * y1;
    ys[warp][lane] = y0; ys[warp][lane + 32] = y1;
    __syncwarp();
    float acc = b1[lane];
#pragma unroll
    for (int k = 0; k < SH; ++k) acc = fmaf(ys[warp][k], W1[k * 32 + lane], acc);
    acc = acc > 0.f ? acc : 0.2f * acc;
    float p = acc * W2[lane];
#pragma unroll
    for (int o = 16; o; o >>= 1) p += __shfl_xor_sync(0xffffffffu, p, o);
    if (lane == 0) out[m] = p + b2[0];
}

extern "C" void kernel_launch(void* const* d_in, const int* in_sizes, int n_in,
                              void* d_out, int out_size) {
    const float* x     = (const float*)d_in[0];
    const int*   ei32  = (const int*)d_in[1];
    const float* W_ih0 = (const float*)d_in[2];
    const float* W_hh0 = (const float*)d_in[3];
    const float* b_ih0 = (const float*)d_in[4];
    const float* b_hh0 = (const float*)d_in[5];
    const float* W_ih1 = (const float*)d_in[6];
    const float* W_hh1 = (const float*)d_in[7];
    const float* b_ih1 = (const float*)d_in[8];
    const float* b_hh1 = (const float*)d_in[9];
    const float* ln1_g = (const float*)d_in[10];
    const float* ln1_b = (const float*)d_in[11];
    const float* gat_W = (const float*)d_in[12];
    const float* att_s = (const float*)d_in[13];
    const float* att_d = (const float*)d_in[14];
    const float* gat_b = (const float*)d_in[15];
    const float* ln2_g = (const float*)d_in[16];
    const float* ln2_b = (const float*)d_in[17];
    const float* regW1 = (const float*)d_in[18];
    const float* regb1 = (const float*)d_in[19];
    const float* regW2 = (const float*)d_in[20];
    const float* regb2 = (const float*)d_in[21];
    float* out = (float*)d_out;

    cudaFuncSetAttribute(gru_all, cudaFuncAttributeMaxDynamicSharedMemorySize, SM_TOT);

    detect_ei_kernel<<<1, 256>>>(ei32);
    prep_pack<<<(Q1N + Q0N + 255) / 256, 256>>>(W_ih1, W_hh1, W_hh0);
    zero_kernel<<<2048, 512>>>();

    gru_all<<<500, 256, SM_TOT>>>(x, W_ih0, b_ih0, b_hh0, b_ih1, b_hh1);

    node_stage1<<<Mn / 8, 256>>>(ln1_g, ln1_b, gat_W, att_s, att_d);
    edge_kernel<<<(ET * HEADS + 255) / 256, 256>>>(ei32);
    node_stage2<<<Mn / 8, 256>>>(gat_b, ln2_g, ln2_b, regW1, regb1, regW2, regb2, out);
}